// round 2
// baseline (speedup 1.0000x reference)
#include <cuda_runtime.h>

typedef unsigned long long ull;

#define NB 32
#define LG 576
#define LL 256
#define NC 512
#define ND 8192
#define MG 20
#define ML 4

// ---------------- device scratch (no allocations allowed) ----------------
__device__ float g_D2[NB * LG * LL];     // 18.9 MB distance^2 matrix
__device__ float g_normg[NB * LG];
__device__ float g_norml[NB * LL];
__device__ ull   g_key_fg[NB * LG];      // feature NN keys, global->local
__device__ ull   g_key_fl[NB * LL];      // feature NN keys, local->global (atomicMin)
__device__ ull   g_key_gg[NB * LG];      // grid NN keys, global->local
__device__ ull   g_key_gl[NB * LL];      // grid NN keys, local->global
__device__ int   g_sel_fg[NB * MG];
__device__ int   g_sel_fl[NB * ML];
__device__ int   g_sel_gg[NB * MG];
__device__ int   g_sel_gl[NB * ML];
__device__ float g_R[2 * 32 * 32];       // raw gram matrices of z_global / z_local
__device__ float g_acc[16];
// acc: 0 var_a, 1 var_b, 2 sum s_j^2 a, 3 sum s_j^2 b, 4 inv-sum,
//      5 mse_fg, 6 mse_fl, 7 mse_gg, 8 mse_gl

__device__ __forceinline__ ull packkey(float d, int i) {
    return (((ull)__float_as_uint(d)) << 32) | (unsigned)i;
}

__device__ float block_reduce(float v, float* sh) {
    __syncthreads();
    int lane = threadIdx.x & 31, wid = threadIdx.x >> 5;
#pragma unroll
    for (int o = 16; o; o >>= 1) v += __shfl_down_sync(0xffffffffu, v, o);
    if (lane == 0) sh[wid] = v;
    __syncthreads();
    float r = 0.f;
    if (wid == 0) {
        int nw = (blockDim.x + 31) >> 5;
        r = (lane < nw) ? sh[lane] : 0.f;
#pragma unroll
        for (int o = 16; o; o >>= 1) r += __shfl_down_sync(0xffffffffu, r, o);
    }
    return r;  // valid on thread 0
}

// ---------------- init ----------------
__global__ void init_kernel() {
    int t = blockIdx.x * blockDim.x + threadIdx.x;
    if (t < 16) g_acc[t] = 0.f;
    for (int i = t; i < NB * LL; i += gridDim.x * blockDim.x) g_key_fl[i] = ~0ULL;
}

// ---------------- row norms of feature maps ----------------
__global__ void norm_kernel(const float* __restrict__ z, int which) {
    __shared__ float sh[8];
    const float4* p = (const float4*)(z + (size_t)blockIdx.x * NC);
    float4 v = p[threadIdx.x];  // blockDim = 128 = NC/4
    float s = v.x * v.x + v.y * v.y + v.z * v.z + v.w * v.w;
    s = block_reduce(s, sh);
    if (threadIdx.x == 0) {
        if (which == 0) g_normg[blockIdx.x] = s;
        else            g_norml[blockIdx.x] = s;
    }
}

// ---------------- feature cdist^2 (GEMM-like) ----------------
// D2[b,l,m] = |zg_l|^2 + |zl_m|^2 - 2 * dot(zg_l, zl_m)
__global__ void __launch_bounds__(256) cdist_kernel(const float* __restrict__ Ag,
                                                    const float* __restrict__ Bg) {
    int bb = blockIdx.z;
    int mo = blockIdx.y * 64;  // row tile in LG
    int no = blockIdx.x * 64;  // col tile in LL
    const float* A  = Ag + (size_t)bb * LG * NC;
    const float* Bm = Bg + (size_t)bb * LL * NC;
    __shared__ float As[16][68];
    __shared__ float Bs[16][68];
    int tid = threadIdx.x;
    int tx = tid & 15, ty = tid >> 4;
    float acc[4][4] = {};
    int lrow = tid >> 2;        // 0..63
    int lcol = (tid & 3) * 4;   // 0,4,8,12
    const float* Aptr = A  + (size_t)(mo + lrow) * NC + lcol;
    const float* Bptr = Bm + (size_t)(no + lrow) * NC + lcol;

    for (int kk = 0; kk < NC; kk += 16) {
        float4 av = *(const float4*)(Aptr + kk);
        float4 bv = *(const float4*)(Bptr + kk);
        As[lcol + 0][lrow] = av.x; As[lcol + 1][lrow] = av.y;
        As[lcol + 2][lrow] = av.z; As[lcol + 3][lrow] = av.w;
        Bs[lcol + 0][lrow] = bv.x; Bs[lcol + 1][lrow] = bv.y;
        Bs[lcol + 2][lrow] = bv.z; Bs[lcol + 3][lrow] = bv.w;
        __syncthreads();
#pragma unroll
        for (int k = 0; k < 16; k++) {
            float4 a4 = *(const float4*)&As[k][ty * 4];
            float4 b4 = *(const float4*)&Bs[k][tx * 4];
            acc[0][0] += a4.x * b4.x; acc[0][1] += a4.x * b4.y;
            acc[0][2] += a4.x * b4.z; acc[0][3] += a4.x * b4.w;
            acc[1][0] += a4.y * b4.x; acc[1][1] += a4.y * b4.y;
            acc[1][2] += a4.y * b4.z; acc[1][3] += a4.y * b4.w;
            acc[2][0] += a4.z * b4.x; acc[2][1] += a4.z * b4.y;
            acc[2][2] += a4.z * b4.z; acc[2][3] += a4.z * b4.w;
            acc[3][0] += a4.w * b4.x; acc[3][1] += a4.w * b4.y;
            acc[3][2] += a4.w * b4.z; acc[3][3] += a4.w * b4.w;
        }
        __syncthreads();
    }

#pragma unroll
    for (int i = 0; i < 4; i++) {
        int row = mo + ty * 4 + i;
        float na = g_normg[bb * LG + row];
        float4 o;
        o.x = na + g_norml[bb * LL + no + tx * 4 + 0] - 2.f * acc[i][0];
        o.y = na + g_norml[bb * LL + no + tx * 4 + 1] - 2.f * acc[i][1];
        o.z = na + g_norml[bb * LL + no + tx * 4 + 2] - 2.f * acc[i][2];
        o.w = na + g_norml[bb * LL + no + tx * 4 + 3] - 2.f * acc[i][3];
        *(float4*)&g_D2[((size_t)bb * LG + row) * LL + no + tx * 4] = o;
    }
}

// ---------------- per-row NN over 256 candidates (one warp per row) ----------------
__global__ void rowmin_kernel() {
    int gw = (blockIdx.x * blockDim.x + threadIdx.x) >> 5;
    int lane = threadIdx.x & 31;
    if (gw >= NB * LG) return;
    const float* row = g_D2 + (size_t)gw * LL;
    float best = 3.4e38f; int bi = 0;
#pragma unroll
    for (int m = 0; m < LL / 32; m++) {
        int idx = lane + m * 32;
        float d = row[idx];
        if (d < best) { best = d; bi = idx; }
    }
#pragma unroll
    for (int o = 16; o; o >>= 1) {
        float od = __shfl_down_sync(0xffffffffu, best, o);
        int   oi = __shfl_down_sync(0xffffffffu, bi, o);
        if (od < best || (od == best && oi < bi)) { best = od; bi = oi; }
    }
    if (lane == 0) g_key_fg[gw] = packkey(best, bi);
}

// ---------------- per-column NN over 576 candidates ----------------
__global__ void colmin_kernel() {
    int bb = blockIdx.x;
    int chunk = blockIdx.y;  // 4 chunks of 144
    int m = threadIdx.x;     // 256 threads
    const float* base = g_D2 + (size_t)bb * LG * LL + m;
    int l0 = chunk * 144;
    float best = 3.4e38f; int bi = 0;
    for (int l = l0; l < l0 + 144; l++) {
        float d = base[(size_t)l * LL];
        if (d < best) { best = d; bi = l; }
    }
    atomicMin(&g_key_fl[bb * LL + m], packkey(best, bi));
}

// ---------------- grid-space NN (C = 2) ----------------
__global__ void gridnn_kernel(const float* __restrict__ gin, const float* __restrict__ gcand,
                              int Lin, int Lc, int dir) {
    int bb = blockIdx.x;
    __shared__ float2 sc[LG];
    const float2* gc = (const float2*)gcand + (size_t)bb * Lc;
    for (int i = threadIdx.x; i < Lc; i += blockDim.x) sc[i] = gc[i];
    __syncthreads();
    const float2* gi = (const float2*)gin + (size_t)bb * Lin;
    ull* out = dir ? g_key_gl : g_key_gg;
    for (int l = threadIdx.x; l < Lin; l += blockDim.x) {
        float2 g = gi[l];
        float best = 3.4e38f; int bi = 0;
        for (int m = 0; m < Lc; m++) {
            float dx = g.x - sc[m].x, dy = g.y - sc[m].y;
            float d = dx * dx + dy * dy;
            if (d < best) { best = d; bi = m; }
        }
        out[(size_t)bb * Lin + l] = packkey(best, bi);
    }
}

// ---------------- exact top-k selection by rank (matches lax.top_k tie-break) ----------------
__global__ void select_kernel(int which) {
    int bb = blockIdx.x;
    const ull* keys; int L, Msel; int* sel;
    if (which == 0)      { keys = g_key_fg; L = LG; Msel = MG; sel = g_sel_fg; }
    else if (which == 1) { keys = g_key_fl; L = LL; Msel = ML; sel = g_sel_fl; }
    else if (which == 2) { keys = g_key_gg; L = LG; Msel = MG; sel = g_sel_gg; }
    else                 { keys = g_key_gl; L = LL; Msel = ML; sel = g_sel_gl; }

    __shared__ ull sk[LG];
    __shared__ unsigned char flag[LG];
    const ull* k = keys + (size_t)bb * L;
    for (int i = threadIdx.x; i < L; i += blockDim.x) sk[i] = k[i];
    __syncthreads();
    for (int i = threadIdx.x; i < L; i += blockDim.x) {
        ull mine = sk[i]; int cnt = 0;
        for (int j = 0; j < L; j++) {
            ull o = sk[j];
            cnt += (o < mine) || (o == mine && j < i);
        }
        flag[i] = (cnt < Msel) ? 1 : 0;
    }
    __syncthreads();
    if (threadIdx.x == 0) {
        int p = 0;
        for (int i = 0; i < L && p < Msel; i++)
            if (flag[i]) sel[bb * Msel + (p++)] = i;
    }
}

// ---------------- gathered MSE accumulation ----------------
__global__ void mse_kernel(const float* __restrict__ fG, const float* __restrict__ fL,
                           int which) {
    __shared__ float sh[8];
    const float* fin; const float* fc; const int* sel; const ull* keys;
    int Lin, Lc, Msel, accIdx;
    if (which == 0)      { fin = fG; fc = fL; sel = g_sel_fg; keys = g_key_fg; Lin = LG; Lc = LL; Msel = MG; accIdx = 5; }
    else if (which == 1) { fin = fL; fc = fG; sel = g_sel_fl; keys = g_key_fl; Lin = LL; Lc = LG; Msel = ML; accIdx = 6; }
    else if (which == 2) { fin = fG; fc = fL; sel = g_sel_gg; keys = g_key_gg; Lin = LG; Lc = LL; Msel = MG; accIdx = 7; }
    else                 { fin = fL; fc = fG; sel = g_sel_gl; keys = g_key_gl; Lin = LL; Lc = LG; Msel = ML; accIdx = 8; }

    int bb = blockIdx.x / Msel, mi = blockIdx.x % Msel;
    int row = sel[bb * Msel + mi];
    int cand = (int)(keys[(size_t)bb * Lin + row] & 0xffffffffULL);
    const float4* p = (const float4*)(fin + ((size_t)bb * Lin + row) * NC);
    const float4* q = (const float4*)(fc + ((size_t)bb * Lc + cand) * NC);
    float s = 0.f;
    for (int t = threadIdx.x; t < NC / 4; t += blockDim.x) {
        float4 x = p[t], y = q[t];
        float dx = x.x - y.x, dy = x.y - y.y, dz = x.z - y.z, dw = x.w - y.w;
        s += dx * dx + dy * dy + dz * dz + dw * dw;
    }
    s = block_reduce(s, sh);
    if (threadIdx.x == 0) atomicAdd(&g_acc[accIdx], s);
}

// ---------------- global VICReg per-dim stats ----------------
__global__ void stats_kernel(const float* __restrict__ a, const float* __restrict__ b) {
    __shared__ float sh[8];
    int j = blockIdx.x * blockDim.x + threadIdx.x;  // 8192 dims
    float sa = 0, sqa = 0, sb = 0, sqb = 0, sd = 0;
#pragma unroll 8
    for (int i = 0; i < 32; i++) {
        float x = a[(size_t)i * ND + j], y = b[(size_t)i * ND + j];
        sa += x; sqa += x * x; sb += y; sqb += y * y;
        float df = x - y; sd += df * df;
    }
    float s_a = sqa - sa * sa * (1.f / 32.f);
    float s_b = sqb - sb * sb * (1.f / 32.f);
    float va = fmaxf(0.f, 1.f - sqrtf(s_a * (1.f / 31.f) + 1e-4f));
    float vb = fmaxf(0.f, 1.f - sqrtf(s_b * (1.f / 31.f) + 1e-4f));
    float r;
    r = block_reduce(va, sh);        if (threadIdx.x == 0) atomicAdd(&g_acc[0], r);
    r = block_reduce(vb, sh);        if (threadIdx.x == 0) atomicAdd(&g_acc[1], r);
    r = block_reduce(s_a * s_a, sh); if (threadIdx.x == 0) atomicAdd(&g_acc[2], r);
    r = block_reduce(s_b * s_b, sh); if (threadIdx.x == 0) atomicAdd(&g_acc[3], r);
    r = block_reduce(sd, sh);        if (threadIdx.x == 0) atomicAdd(&g_acc[4], r);
}

// ---------------- 32x32 raw gram matrices ----------------
__global__ void gram_kernel(const float* __restrict__ a, const float* __restrict__ b) {
    __shared__ float sh[8];
    int blk = blockIdx.x;  // 0..2047
    const float* z = (blk < 1024) ? a : b;
    int rem = blk & 1023;
    int i = rem >> 5, k = rem & 31;
    const float4* p = (const float4*)(z + (size_t)i * ND);
    const float4* q = (const float4*)(z + (size_t)k * ND);
    float s = 0.f;
    for (int t = threadIdx.x; t < ND / 4; t += blockDim.x) {
        float4 x = p[t], y = q[t];
        s += x.x * y.x + x.y * y.y + x.z * y.z + x.w * y.w;
    }
    s = block_reduce(s, sh);
    if (threadIdx.x == 0) g_R[blk] = s;
}

// ---------------- final combine ----------------
__global__ void final_kernel(float* __restrict__ out, int out_size) {
    __shared__ float sR[1024];
    __shared__ float rowsum[32];
    __shared__ float sh[8];
    __shared__ float covG[2];
    __shared__ float qsh;
    for (int mat = 0; mat < 2; mat++) {
        for (int t = threadIdx.x; t < 1024; t += blockDim.x) sR[t] = g_R[mat * 1024 + t];
        __syncthreads();
        if (threadIdx.x < 32) {
            float s = 0.f;
            for (int k = 0; k < 32; k++) s += sR[threadIdx.x * 32 + k];
            rowsum[threadIdx.x] = s;
        }
        __syncthreads();
        if (threadIdx.x == 0) {
            float t = 0.f;
            for (int i = 0; i < 32; i++) t += rowsum[i];
            qsh = t * (1.f / 1024.f);
        }
        __syncthreads();
        float q = qsh;
        float part = 0.f;
        for (int t = threadIdx.x; t < 1024; t += blockDim.x) {
            int i = t >> 5, k = t & 31;
            float g = sR[t] - rowsum[i] * (1.f / 32.f) - rowsum[k] * (1.f / 32.f) + q;
            part += g * g;
        }
        float tot = block_reduce(part, sh);
        if (threadIdx.x == 0) covG[mat] = tot;
        __syncthreads();
    }
    if (threadIdx.x == 0) {
        float inv_g = g_acc[4] * (1.f / (32.f * 8192.f));
        float v = 0.5f * (g_acc[0] + g_acc[1]) * (1.f / 8192.f);
        float cov = ((covG[0] - g_acc[2]) + (covG[1] - g_acc[3])) * (1.f / (31.f * 31.f * 8192.f));
        float global_loss = 25.f * inv_g + 25.f * v + 1.f * cov;
        float mfg = g_acc[5] * (1.f / (32.f * MG * NC));
        float mfl = g_acc[6] * (1.f / (32.f * ML * NC));
        float mgg = g_acc[7] * (1.f / (32.f * MG * NC));
        float mgl = g_acc[8] * (1.f / (32.f * ML * NC));
        float local_loss = 25.f * (0.5f * (mfg + mfl) + 0.5f * (mgg + mgl));
        float res = 0.25f * global_loss + 0.75f * local_loss;
        for (int i = 0; i < out_size; i++) out[i] = res;
    }
}

extern "C" void kernel_launch(void* const* d_in, const int* in_sizes, int n_in,
                              void* d_out, int out_size) {
    (void)in_sizes; (void)n_in;
    const float* zg = (const float*)d_in[0];   // (32, 8192)
    const float* zl = (const float*)d_in[1];   // (32, 8192)
    const float* fg = (const float*)d_in[2];   // (32, 576, 512)
    const float* fl = (const float*)d_in[3];   // (32, 256, 512)
    const float* gg = (const float*)d_in[4];   // (32, 576, 2)
    const float* gl = (const float*)d_in[5];   // (32, 256, 2)
    float* out = (float*)d_out;

    init_kernel<<<32, 256>>>();

    // global VICReg pieces
    stats_kernel<<<ND / 256, 256>>>(zg, zl);
    gram_kernel<<<2048, 256>>>(zg, zl);

    // feature-space distances + NN
    norm_kernel<<<NB * LG, 128>>>(fg, 0);
    norm_kernel<<<NB * LL, 128>>>(fl, 1);
    {
        dim3 grid(LL / 64, LG / 64, NB);
        cdist_kernel<<<grid, 256>>>(fg, fl);
    }
    rowmin_kernel<<<(NB * LG) / 8, 256>>>();
    {
        dim3 grid(NB, 4);
        colmin_kernel<<<grid, 256>>>();
    }

    // grid-space NN
    gridnn_kernel<<<NB, 256>>>(gg, gl, LG, LL, 0);
    gridnn_kernel<<<NB, 256>>>(gl, gg, LL, LG, 1);

    // top-k selection (exact tie-break)
    select_kernel<<<NB, 256>>>(0);
    select_kernel<<<NB, 256>>>(1);
    select_kernel<<<NB, 256>>>(2);
    select_kernel<<<NB, 256>>>(3);

    // gathered MSEs
    mse_kernel<<<NB * MG, 128>>>(fg, fl, 0);
    mse_kernel<<<NB * ML, 128>>>(fg, fl, 1);
    mse_kernel<<<NB * MG, 128>>>(fg, fl, 2);
    mse_kernel<<<NB * ML, 128>>>(fg, fl, 3);

    final_kernel<<<1, 256>>>(out, out_size);
}

// round 3
// speedup vs baseline: 1.0494x; 1.0494x over previous
#include <cuda_runtime.h>

typedef unsigned long long ull;

#define NB 32
#define LG 576
#define LL 256
#define NC 512
#define ND 8192
#define MG 20
#define ML 4

#define TM 64
#define TN 128
#define TK 16

// ---------------- device scratch (no allocations allowed) ----------------
__device__ ull   g_key_fg[NB * LG];      // feature NN keys, global->local
__device__ ull   g_key_fl[NB * LL];      // feature NN keys, local->global
__device__ ull   g_key_gg[NB * LG];      // grid NN keys, global->local
__device__ ull   g_key_gl[NB * LL];      // grid NN keys, local->global
__device__ int   g_sel_fg[NB * MG];
__device__ int   g_sel_fl[NB * ML];
__device__ int   g_sel_gg[NB * MG];
__device__ int   g_sel_gl[NB * ML];
__device__ float g_Rp[2][32][1024];      // split-K gram partials
__device__ float g_acc[16];
// acc: 0 var_a, 1 var_b, 2 sum s_j^2 a, 3 sum s_j^2 b, 4 inv-sum,
//      5 mse_fg, 6 mse_fl, 7 mse_gg, 8 mse_gl

__device__ __forceinline__ ull packkey(float d, int i) {
    return (((ull)__float_as_uint(d)) << 32) | (unsigned)i;
}

__device__ float block_reduce(float v, float* sh) {
    __syncthreads();
    int lane = threadIdx.x & 31, wid = threadIdx.x >> 5;
#pragma unroll
    for (int o = 16; o; o >>= 1) v += __shfl_down_sync(0xffffffffu, v, o);
    if (lane == 0) sh[wid] = v;
    __syncthreads();
    float r = 0.f;
    if (wid == 0) {
        int nw = (blockDim.x + 31) >> 5;
        r = (lane < nw) ? sh[lane] : 0.f;
#pragma unroll
        for (int o = 16; o; o >>= 1) r += __shfl_down_sync(0xffffffffu, r, o);
    }
    return r;  // valid on thread 0
}

// ---------------- init ----------------
__global__ void init_kernel() {
    int t = blockIdx.x * blockDim.x + threadIdx.x;
    int stride = gridDim.x * blockDim.x;
    if (t < 16) g_acc[t] = 0.f;
    for (int i = t; i < NB * LG; i += stride) g_key_fg[i] = ~0ULL;
    for (int i = t; i < NB * LL; i += stride) g_key_fl[i] = ~0ULL;
}

// ---------------- fused feature cdist^2 + norms + row/col argmin ----------------
// d2[b,l,m] = |zg_l|^2 + |zl_m|^2 - 2*dot(zg_l, zl_m); never materialized.
__global__ void __launch_bounds__(256) cdist_fused_kernel(const float* __restrict__ Ag,
                                                          const float* __restrict__ Bg) {
    int bb = blockIdx.z;
    int mo = blockIdx.y * TM;   // row tile in LG
    int no = blockIdx.x * TN;   // col tile in LL
    const float* A = Ag + (size_t)bb * LG * NC;
    const float* B = Bg + (size_t)bb * LL * NC;

    __shared__ float As[TK][TM + 4];
    __shared__ float Bs[TK][TN + 4];
    __shared__ float rowN[TM];
    __shared__ float colN[TN];
    __shared__ ull   colKey[TN];

    int tid = threadIdx.x;
    int tx = tid & 15;          // col group: cols tx*8 .. tx*8+7
    int ty = tid >> 4;          // row group: rows ty*4 .. ty*4+3

    // loader roles
    int arow = tid >> 2, acol = (tid & 3) * 4;   // A: 64 rows x 16 k, 4 floats/thread
    int brow = tid >> 1, bcol = (tid & 1) * 8;   // B: 128 rows x 16 k, 8 floats/thread
    const float* Ap = A + (size_t)(mo + arow) * NC + acol;
    const float* Bp = B + (size_t)(no + brow) * NC + bcol;

    if (tid < TN) colKey[tid] = ~0ULL;

    float acc[4][8] = {};
    float nA = 0.f, nB = 0.f;

    for (int kk = 0; kk < NC; kk += TK) {
        float4 av  = *(const float4*)(Ap + kk);
        float4 bv0 = *(const float4*)(Bp + kk);
        float4 bv1 = *(const float4*)(Bp + kk + 4);
        As[acol + 0][arow] = av.x; As[acol + 1][arow] = av.y;
        As[acol + 2][arow] = av.z; As[acol + 3][arow] = av.w;
        nA += av.x * av.x + av.y * av.y + av.z * av.z + av.w * av.w;
        Bs[bcol + 0][brow] = bv0.x; Bs[bcol + 1][brow] = bv0.y;
        Bs[bcol + 2][brow] = bv0.z; Bs[bcol + 3][brow] = bv0.w;
        Bs[bcol + 4][brow] = bv1.x; Bs[bcol + 5][brow] = bv1.y;
        Bs[bcol + 6][brow] = bv1.z; Bs[bcol + 7][brow] = bv1.w;
        nB += bv0.x * bv0.x + bv0.y * bv0.y + bv0.z * bv0.z + bv0.w * bv0.w
            + bv1.x * bv1.x + bv1.y * bv1.y + bv1.z * bv1.z + bv1.w * bv1.w;
        __syncthreads();
#pragma unroll
        for (int k = 0; k < TK; k++) {
            float4 a4  = *(const float4*)&As[k][ty * 4];
            float4 b40 = *(const float4*)&Bs[k][tx * 8];
            float4 b41 = *(const float4*)&Bs[k][tx * 8 + 4];
            float ar[4] = {a4.x, a4.y, a4.z, a4.w};
            float br[8] = {b40.x, b40.y, b40.z, b40.w, b41.x, b41.y, b41.z, b41.w};
#pragma unroll
            for (int i = 0; i < 4; i++)
#pragma unroll
                for (int j = 0; j < 8; j++)
                    acc[i][j] = fmaf(ar[i], br[j], acc[i][j]);
        }
        __syncthreads();
    }

    // finish norms: A partials live on 4 consecutive lanes, B partials on 2
    nA += __shfl_xor_sync(0xffffffffu, nA, 1);
    nA += __shfl_xor_sync(0xffffffffu, nA, 2);
    if ((tid & 3) == 0) rowN[arow] = nA;
    nB += __shfl_xor_sync(0xffffffffu, nB, 1);
    if ((tid & 1) == 0) colN[brow] = nB;
    __syncthreads();

    // turn acc into d2 in-place
    float rN[4];
#pragma unroll
    for (int i = 0; i < 4; i++) rN[i] = rowN[ty * 4 + i];
#pragma unroll
    for (int j = 0; j < 8; j++) {
        float cN = colN[tx * 8 + j];
#pragma unroll
        for (int i = 0; i < 4; i++)
            acc[i][j] = rN[i] + cN - 2.f * acc[i][j];
    }

    // row argmin: min over 8 local cols, then across 16 tx lanes (contiguous)
#pragma unroll
    for (int i = 0; i < 4; i++) {
        ull key = ~0ULL;
#pragma unroll
        for (int j = 0; j < 8; j++) {
            ull k = packkey(acc[i][j], no + tx * 8 + j);
            key = (k < key) ? k : key;
        }
#pragma unroll
        for (int o = 1; o < 16; o <<= 1) {
            ull ok = __shfl_xor_sync(0xffffffffu, key, o);
            key = (ok < key) ? ok : key;
        }
        if (tx == 0) atomicMin(&g_key_fg[(size_t)bb * LG + mo + ty * 4 + i], key);
    }

    // col argmin: min over 4 local rows, pair-reduce across warp halves, then smem atomics
#pragma unroll
    for (int j = 0; j < 8; j++) {
        ull key = ~0ULL;
#pragma unroll
        for (int i = 0; i < 4; i++) {
            ull k = packkey(acc[i][j], mo + ty * 4 + i);
            key = (k < key) ? k : key;
        }
        ull ok = __shfl_xor_sync(0xffffffffu, key, 16);
        key = (ok < key) ? ok : key;
        if ((ty & 1) == 0) atomicMin(&colKey[tx * 8 + j], key);
    }
    __syncthreads();
    if (tid < TN) atomicMin(&g_key_fl[(size_t)bb * LL + no + tid], colKey[tid]);
}

// ---------------- grid-space NN (C = 2), both directions ----------------
__global__ void gridnn_kernel(const float* __restrict__ gg_in, const float* __restrict__ gl_in) {
    int bb = blockIdx.x;
    int dir = blockIdx.y;  // 0: global->local, 1: local->global
    int Lin = dir ? LL : LG;
    int Lc  = dir ? LG : LL;
    const float* gin   = dir ? gl_in : gg_in;
    const float* gcand = dir ? gg_in : gl_in;
    __shared__ float2 sc[LG];
    const float2* gc = (const float2*)gcand + (size_t)bb * Lc;
    for (int i = threadIdx.x; i < Lc; i += blockDim.x) sc[i] = gc[i];
    __syncthreads();
    const float2* gi = (const float2*)gin + (size_t)bb * Lin;
    ull* out = dir ? g_key_gl : g_key_gg;
    for (int l = threadIdx.x; l < Lin; l += blockDim.x) {
        float2 g = gi[l];
        float best = 3.4e38f; int bi = 0;
        for (int m = 0; m < Lc; m++) {
            float dx = g.x - sc[m].x, dy = g.y - sc[m].y;
            float d = dx * dx + dy * dy;
            if (d < best) { best = d; bi = m; }
        }
        out[(size_t)bb * Lin + l] = packkey(best, bi);
    }
}

// ---------------- exact top-k selection by rank ----------------
__global__ void select_kernel() {
    int bb = blockIdx.x;
    int which = blockIdx.y;
    const ull* keys; int L, Msel; int* sel;
    if (which == 0)      { keys = g_key_fg; L = LG; Msel = MG; sel = g_sel_fg; }
    else if (which == 1) { keys = g_key_fl; L = LL; Msel = ML; sel = g_sel_fl; }
    else if (which == 2) { keys = g_key_gg; L = LG; Msel = MG; sel = g_sel_gg; }
    else                 { keys = g_key_gl; L = LL; Msel = ML; sel = g_sel_gl; }

    __shared__ ull sk[LG];
    __shared__ unsigned char flag[LG];
    const ull* k = keys + (size_t)bb * L;
    for (int i = threadIdx.x; i < L; i += blockDim.x) sk[i] = k[i];
    __syncthreads();
    for (int i = threadIdx.x; i < L; i += blockDim.x) {
        ull mine = sk[i]; int cnt = 0;
        for (int j = 0; j < L; j++) {
            ull o = sk[j];
            cnt += (o < mine) || (o == mine && j < i);
        }
        flag[i] = (cnt < Msel) ? 1 : 0;
    }
    __syncthreads();
    if (threadIdx.x == 0) {
        int p = 0;
        for (int i = 0; i < L && p < Msel; i++)
            if (flag[i]) sel[bb * Msel + (p++)] = i;
    }
}

// ---------------- gathered MSE accumulation (all 4 sections in one launch) ----------------
__global__ void mse_kernel(const float* __restrict__ fG, const float* __restrict__ fL) {
    __shared__ float sh[8];
    int bb = blockIdx.x / 48;
    int r  = blockIdx.x % 48;
    int which, mi;
    if (r < MG)              { which = 0; mi = r; }
    else if (r < MG + ML)    { which = 1; mi = r - MG; }
    else if (r < 2*MG + ML)  { which = 2; mi = r - MG - ML; }
    else                     { which = 3; mi = r - 2*MG - ML; }

    const float* fin; const float* fc; const int* sel; const ull* keys;
    int Lin, Lc, Msel, accIdx;
    if (which == 0)      { fin = fG; fc = fL; sel = g_sel_fg; keys = g_key_fg; Lin = LG; Lc = LL; Msel = MG; accIdx = 5; }
    else if (which == 1) { fin = fL; fc = fG; sel = g_sel_fl; keys = g_key_fl; Lin = LL; Lc = LG; Msel = ML; accIdx = 6; }
    else if (which == 2) { fin = fG; fc = fL; sel = g_sel_gg; keys = g_key_gg; Lin = LG; Lc = LL; Msel = MG; accIdx = 7; }
    else                 { fin = fL; fc = fG; sel = g_sel_gl; keys = g_key_gl; Lin = LL; Lc = LG; Msel = ML; accIdx = 8; }

    int row = sel[bb * Msel + mi];
    int cand = (int)(keys[(size_t)bb * Lin + row] & 0xffffffffULL);
    const float4* p = (const float4*)(fin + ((size_t)bb * Lin + row) * NC);
    const float4* q = (const float4*)(fc + ((size_t)bb * Lc + cand) * NC);
    float s = 0.f;
    for (int t = threadIdx.x; t < NC / 4; t += blockDim.x) {
        float4 x = p[t], y = q[t];
        float dx = x.x - y.x, dy = x.y - y.y, dz = x.z - y.z, dw = x.w - y.w;
        s += dx * dx + dy * dy + dz * dz + dw * dw;
    }
    s = block_reduce(s, sh);
    if (threadIdx.x == 0) atomicAdd(&g_acc[accIdx], s);
}

// ---------------- global VICReg per-dim stats ----------------
__global__ void stats_kernel(const float* __restrict__ a, const float* __restrict__ b) {
    __shared__ float sh[8];
    int j = blockIdx.x * blockDim.x + threadIdx.x;  // 8192 dims
    float sa = 0, sqa = 0, sb = 0, sqb = 0, sd = 0;
#pragma unroll 8
    for (int i = 0; i < 32; i++) {
        float x = a[(size_t)i * ND + j], y = b[(size_t)i * ND + j];
        sa += x; sqa += x * x; sb += y; sqb += y * y;
        float df = x - y; sd += df * df;
    }
    float s_a = sqa - sa * sa * (1.f / 32.f);
    float s_b = sqb - sb * sb * (1.f / 32.f);
    float va = fmaxf(0.f, 1.f - sqrtf(s_a * (1.f / 31.f) + 1e-4f));
    float vb = fmaxf(0.f, 1.f - sqrtf(s_b * (1.f / 31.f) + 1e-4f));
    float r;
    r = block_reduce(va, sh);        if (threadIdx.x == 0) atomicAdd(&g_acc[0], r);
    r = block_reduce(vb, sh);        if (threadIdx.x == 0) atomicAdd(&g_acc[1], r);
    r = block_reduce(s_a * s_a, sh); if (threadIdx.x == 0) atomicAdd(&g_acc[2], r);
    r = block_reduce(s_b * s_b, sh); if (threadIdx.x == 0) atomicAdd(&g_acc[3], r);
    r = block_reduce(sd, sh);        if (threadIdx.x == 0) atomicAdd(&g_acc[4], r);
}

// ---------------- split-K 32x32 gram partials (deterministic) ----------------
__global__ void __launch_bounds__(64) gram_kernel(const float* __restrict__ a,
                                                  const float* __restrict__ b) {
    int mat = blockIdx.x >> 5;
    int chunk = blockIdx.x & 31;
    int d0 = chunk * 256;
    const float* z = mat ? b : a;
    __shared__ float s[32][257];
    int tid = threadIdx.x;
    // load 32 rows x 256 dims
    for (int idx = tid; idx < 2048; idx += 64) {
        int row = idx >> 6, c4 = idx & 63;
        float4 v = *(const float4*)(z + (size_t)row * ND + d0 + c4 * 4);
        s[row][c4 * 4 + 0] = v.x; s[row][c4 * 4 + 1] = v.y;
        s[row][c4 * 4 + 2] = v.z; s[row][c4 * 4 + 3] = v.w;
    }
    __syncthreads();
    int ia = (tid >> 3) * 4, kb = (tid & 7) * 4;
    float c[4][4] = {};
    for (int d = 0; d < 256; d++) {
        float av[4], bv[4];
#pragma unroll
        for (int i = 0; i < 4; i++) av[i] = s[ia + i][d];
#pragma unroll
        for (int j = 0; j < 4; j++) bv[j] = s[kb + j][d];
#pragma unroll
        for (int i = 0; i < 4; i++)
#pragma unroll
            for (int j = 0; j < 4; j++)
                c[i][j] = fmaf(av[i], bv[j], c[i][j]);
    }
#pragma unroll
    for (int i = 0; i < 4; i++)
#pragma unroll
        for (int j = 0; j < 4; j++)
            g_Rp[mat][chunk][(ia + i) * 32 + kb + j] = c[i][j];
}

// ---------------- final combine ----------------
__global__ void final_kernel(float* __restrict__ out, int out_size) {
    __shared__ float sR[1024];
    __shared__ float rowsum[32];
    __shared__ float sh[8];
    __shared__ float covG[2];
    __shared__ float qsh;
    for (int mat = 0; mat < 2; mat++) {
        for (int t = threadIdx.x; t < 1024; t += blockDim.x) {
            float s = 0.f;
            for (int c = 0; c < 32; c++) s += g_Rp[mat][c][t];
            sR[t] = s;
        }
        __syncthreads();
        if (threadIdx.x < 32) {
            float s = 0.f;
            for (int k = 0; k < 32; k++) s += sR[threadIdx.x * 32 + k];
            rowsum[threadIdx.x] = s;
        }
        __syncthreads();
        if (threadIdx.x == 0) {
            float t = 0.f;
            for (int i = 0; i < 32; i++) t += rowsum[i];
            qsh = t * (1.f / 1024.f);
        }
        __syncthreads();
        float q = qsh;
        float part = 0.f;
        for (int t = threadIdx.x; t < 1024; t += blockDim.x) {
            int i = t >> 5, k = t & 31;
            float g = sR[t] - rowsum[i] * (1.f / 32.f) - rowsum[k] * (1.f / 32.f) + q;
            part += g * g;
        }
        float tot = block_reduce(part, sh);
        if (threadIdx.x == 0) covG[mat] = tot;
        __syncthreads();
    }
    if (threadIdx.x == 0) {
        float inv_g = g_acc[4] * (1.f / (32.f * 8192.f));
        float v = 0.5f * (g_acc[0] + g_acc[1]) * (1.f / 8192.f);
        float cov = ((covG[0] - g_acc[2]) + (covG[1] - g_acc[3])) * (1.f / (31.f * 31.f * 8192.f));
        float global_loss = 25.f * inv_g + 25.f * v + 1.f * cov;
        float mfg = g_acc[5] * (1.f / (32.f * MG * NC));
        float mfl = g_acc[6] * (1.f / (32.f * ML * NC));
        float mgg = g_acc[7] * (1.f / (32.f * MG * NC));
        float mgl = g_acc[8] * (1.f / (32.f * ML * NC));
        float local_loss = 25.f * (0.5f * (mfg + mfl) + 0.5f * (mgg + mgl));
        float res = 0.25f * global_loss + 0.75f * local_loss;
        for (int i = 0; i < out_size; i++) out[i] = res;
    }
}

extern "C" void kernel_launch(void* const* d_in, const int* in_sizes, int n_in,
                              void* d_out, int out_size) {
    (void)in_sizes; (void)n_in;
    const float* zg = (const float*)d_in[0];   // (32, 8192)
    const float* zl = (const float*)d_in[1];   // (32, 8192)
    const float* fg = (const float*)d_in[2];   // (32, 576, 512)
    const float* fl = (const float*)d_in[3];   // (32, 256, 512)
    const float* gg = (const float*)d_in[4];   // (32, 576, 2)
    const float* gl = (const float*)d_in[5];   // (32, 256, 2)
    float* out = (float*)d_out;

    init_kernel<<<72, 256>>>();

    // global VICReg pieces
    stats_kernel<<<ND / 256, 256>>>(zg, zl);
    gram_kernel<<<64, 64>>>(zg, zl);

    // fused feature-space distances + NN argmins (no D2 materialization)
    {
        dim3 grid(LL / TN, LG / TM, NB);
        cdist_fused_kernel<<<grid, 256>>>(fg, fl);
    }

    // grid-space NN, both directions
    {
        dim3 grid(NB, 2);
        gridnn_kernel<<<grid, 256>>>(gg, gl);
    }

    // top-k selection (exact tie-break), all 4 sections
    {
        dim3 grid(NB, 4);
        select_kernel<<<grid, 256>>>();
    }

    // gathered MSEs, all 4 sections
    mse_kernel<<<NB * 48, 128>>>(fg, fl);

    final_kernel<<<1, 256>>>(out, out_size);
}

// round 4
// speedup vs baseline: 1.8433x; 1.7566x over previous
#include <cuda_runtime.h>

typedef unsigned long long ull;
typedef unsigned int u32;

#define NB 32
#define LG 576
#define LL 256
#define NC 512
#define ND 8192
#define MG 20
#define ML 4

// ---------------- device scratch (no allocations allowed) ----------------
__device__ ull   g_key_fg[NB * LG];
__device__ ull   g_key_fl[NB * LL];
__device__ ull   g_key_gg[NB * LG];
__device__ ull   g_key_gl[NB * LL];
__device__ int   g_sel_fg[NB * MG];
__device__ int   g_sel_fl[NB * ML];
__device__ int   g_sel_gg[NB * MG];
__device__ int   g_sel_gl[NB * ML];
__device__ float g_normg[NB * LG];
__device__ float g_norml[NB * LL];
__device__ float g_Rp[2][32][1024];
__device__ float g_acc[16];
// acc: 0 var_a, 1 var_b, 2 sum s_j^2 a, 3 sum s_j^2 b, 4 inv-sum,
//      5 mse_fg, 6 mse_fl, 7 mse_gg, 8 mse_gl

__device__ __forceinline__ ull packkey(float d, int i) {
    return (((ull)__float_as_uint(d)) << 32) | (unsigned)i;
}

__device__ __forceinline__ u32 f2tf(float x) {
    u32 r; asm("cvt.rna.tf32.f32 %0, %1;" : "=r"(r) : "f"(x)); return r;
}

#define MMA_TF32(C, A, B0, B1)                                              \
    asm volatile("mma.sync.aligned.m16n8k8.row.col.f32.tf32.tf32.f32 "      \
                 "{%0,%1,%2,%3}, {%4,%5,%6,%7}, {%8,%9}, {%0,%1,%2,%3};"    \
                 : "+f"((C)[0]), "+f"((C)[1]), "+f"((C)[2]), "+f"((C)[3])   \
                 : "r"((A)[0]), "r"((A)[1]), "r"((A)[2]), "r"((A)[3]),      \
                   "r"(B0), "r"(B1))

__device__ float block_reduce(float v, float* sh) {
    __syncthreads();
    int lane = threadIdx.x & 31, wid = threadIdx.x >> 5;
#pragma unroll
    for (int o = 16; o; o >>= 1) v += __shfl_down_sync(0xffffffffu, v, o);
    if (lane == 0) sh[wid] = v;
    __syncthreads();
    float r = 0.f;
    if (wid == 0) {
        int nw = (blockDim.x + 31) >> 5;
        r = (lane < nw) ? sh[lane] : 0.f;
#pragma unroll
        for (int o = 16; o; o >>= 1) r += __shfl_down_sync(0xffffffffu, r, o);
    }
    return r;  // valid on thread 0
}

// ================= fused pre-kernel: init + stats + gram + norms =================
// blocks 0..31: per-dim VICReg stats; 32..95: split-K gram; 96..127: fl norms;
// 128..223: fg norms; 224: init.
__global__ void __launch_bounds__(256) fused_pre(const float* __restrict__ za,
                                                 const float* __restrict__ zb,
                                                 const float* __restrict__ fg,
                                                 const float* __restrict__ fl) {
    __shared__ float sh[8];
    int blk = blockIdx.x, tid = threadIdx.x;
    if (blk < 32) {
        int j = blk * 256 + tid;
        float sa = 0, sqa = 0, sb = 0, sqb = 0, sd = 0;
#pragma unroll 8
        for (int i = 0; i < 32; i++) {
            float x = za[(size_t)i * ND + j], y = zb[(size_t)i * ND + j];
            sa += x; sqa += x * x; sb += y; sqb += y * y;
            float df = x - y; sd += df * df;
        }
        float s_a = sqa - sa * sa * (1.f / 32.f);
        float s_b = sqb - sb * sb * (1.f / 32.f);
        float va = fmaxf(0.f, 1.f - sqrtf(s_a * (1.f / 31.f) + 1e-4f));
        float vb = fmaxf(0.f, 1.f - sqrtf(s_b * (1.f / 31.f) + 1e-4f));
        float r;
        r = block_reduce(va, sh);        if (tid == 0) atomicAdd(&g_acc[0], r);
        r = block_reduce(vb, sh);        if (tid == 0) atomicAdd(&g_acc[1], r);
        r = block_reduce(s_a * s_a, sh); if (tid == 0) atomicAdd(&g_acc[2], r);
        r = block_reduce(s_b * s_b, sh); if (tid == 0) atomicAdd(&g_acc[3], r);
        r = block_reduce(sd, sh);        if (tid == 0) atomicAdd(&g_acc[4], r);
    } else if (blk < 96) {
        __shared__ float s[32][257];
        int idx = blk - 32;
        int mat = idx >> 5, chunk = idx & 31;
        int d0 = chunk * 256;
        const float* z = mat ? zb : za;
        for (int i = tid; i < 2048; i += 256) {
            int row = i >> 6, c4 = i & 63;
            float4 v = *(const float4*)(z + (size_t)row * ND + d0 + c4 * 4);
            s[row][c4 * 4 + 0] = v.x; s[row][c4 * 4 + 1] = v.y;
            s[row][c4 * 4 + 2] = v.z; s[row][c4 * 4 + 3] = v.w;
        }
        __syncthreads();
        int ia = tid >> 3, kb = (tid & 7) * 4;
        float c[4] = {};
        for (int d = 0; d < 256; d++) {
            float av = s[ia][d];
#pragma unroll
            for (int j = 0; j < 4; j++) c[j] = fmaf(av, s[kb + j][d], c[j]);
        }
#pragma unroll
        for (int j = 0; j < 4; j++) g_Rp[mat][chunk][ia * 32 + kb + j] = c[j];
    } else if (blk < 224) {
        const float* src; float* dst; int rows, w, wtot;
        if (blk < 128) { src = fl; dst = g_norml; rows = NB * LL; w = (blk - 96) * 8 + (tid >> 5); wtot = 32 * 8; }
        else           { src = fg; dst = g_normg; rows = NB * LG; w = (blk - 128) * 8 + (tid >> 5); wtot = 96 * 8; }
        int lane = tid & 31;
        for (int row = w; row < rows; row += wtot) {
            const float4* p = (const float4*)(src + (size_t)row * NC);
            float s = 0.f;
#pragma unroll
            for (int i = 0; i < 4; i++) {
                float4 v = p[lane + i * 32];
                s += v.x * v.x + v.y * v.y + v.z * v.z + v.w * v.w;
            }
#pragma unroll
            for (int o = 16; o; o >>= 1) s += __shfl_down_sync(0xffffffffu, s, o);
            if (lane == 0) dst[row] = s;
        }
    } else {
        if (tid < 16) g_acc[tid] = 0.f;
        for (int i = tid; i < NB * LL; i += 256) g_key_fl[i] = ~0ULL;
    }
}

// ================= tensor-core cdist^2 + row/col argmin =================
// block = (mtile, batch); tile M=64, N=256 (full LL), K=512 in chunks of 32.
// Smem holds tf32 fragments in fragment-major layout with XOR swizzle:
// conflict-free STS.128 writes and per-lane LDS.32 reads.
__global__ void __launch_bounds__(256, 2) cdist_mma(const float* __restrict__ Ag,
                                                    const float* __restrict__ Bg) {
    int bb = blockIdx.y;
    int mo = blockIdx.x * 64;
    const float* A = Ag + (size_t)bb * LG * NC;
    const float* B = Bg + (size_t)bb * LL * NC;

    __shared__ u32 As[4 * 4 * 4 * 32];    // [ks][mfrag][reg][lane^swz]
    __shared__ u32 Bs[4 * 32 * 2 * 32];   // [ks][nfrag][reg][lane^swz]
    __shared__ ull rowKey[64];
    __shared__ ull colKey[LL];

    int tid = threadIdx.x, lane = tid & 31, warp = tid >> 5;
    int mw = warp >> 2, nw = warp & 3;
    if (tid < 64) rowKey[tid] = ~0ULL;
    colKey[tid] = ~0ULL;

    float acc[2][8][4];
#pragma unroll
    for (int i = 0; i < 2; i++)
#pragma unroll
        for (int j = 0; j < 8; j++)
#pragma unroll
            for (int k = 0; k < 4; k++) acc[i][j][k] = 0.f;

    for (int ch = 0; ch < 16; ch++) {
        int koff = ch * 32;
#pragma unroll
        for (int i = 0; i < 2; i++) {
            int f = tid + i * 256;
            int r = f >> 3, c0 = (f & 7) * 4;
            float4 v = *(const float4*)(A + (size_t)(mo + r) * NC + koff + c0);
            int ks = c0 >> 3, half = (c0 & 7) >> 2;
            int reg = half * 2 + ((r & 15) >> 3);
            int lb = (((r & 7) * 4) ^ (ks << 2) ^ (half << 4));
            uint4 o = make_uint4(f2tf(v.x), f2tf(v.y), f2tf(v.z), f2tf(v.w));
            *(uint4*)&As[(((ks * 4 + (r >> 4)) * 4 + reg) * 32) + lb] = o;
        }
#pragma unroll
        for (int i = 0; i < 8; i++) {
            int f = tid + i * 256;
            int n = f >> 3, c0 = (f & 7) * 4;
            float4 v = *(const float4*)(B + (size_t)n * NC + koff + c0);
            int ks = c0 >> 3, reg = (c0 & 7) >> 2;
            int lb = (((n & 7) * 4) ^ (ks << 2) ^ (reg << 4));
            uint4 o = make_uint4(f2tf(v.x), f2tf(v.y), f2tf(v.z), f2tf(v.w));
            *(uint4*)&Bs[(((ks * 32 + (n >> 3)) * 2 + reg) * 32) + lb] = o;
        }
        __syncthreads();
#pragma unroll
        for (int ks = 0; ks < 4; ks++) {
            u32 a[2][4];
#pragma unroll
            for (int m2 = 0; m2 < 2; m2++) {
                int mf = mw * 2 + m2;
                int base = ((ks * 4 + mf) * 4) * 32;
#pragma unroll
                for (int rg = 0; rg < 4; rg++)
                    a[m2][rg] = As[base + rg * 32 + (lane ^ (ks << 2) ^ ((rg >> 1) << 4))];
            }
#pragma unroll
            for (int n2 = 0; n2 < 8; n2++) {
                int nf = nw * 8 + n2;
                u32 b0 = Bs[((ks * 32 + nf) * 2 + 0) * 32 + (lane ^ (ks << 2))];
                u32 b1 = Bs[((ks * 32 + nf) * 2 + 1) * 32 + (lane ^ (ks << 2) ^ 16)];
                MMA_TF32(acc[0][n2], a[0], b0, b1);
                MMA_TF32(acc[1][n2], a[1], b0, b1);
            }
        }
        __syncthreads();
    }

    // ---- epilogue: d2 = na + nb - 2*dot, packed-key argmins ----
    float naR[2][2], nbC[8][2];
#pragma unroll
    for (int m2 = 0; m2 < 2; m2++)
#pragma unroll
        for (int rh = 0; rh < 2; rh++)
            naR[m2][rh] = g_normg[bb * LG + mo + (mw * 2 + m2) * 16 + (lane >> 2) + rh * 8];
#pragma unroll
    for (int n2 = 0; n2 < 8; n2++)
#pragma unroll
        for (int h = 0; h < 2; h++)
            nbC[n2][h] = g_norml[bb * LL + nw * 64 + n2 * 8 + (lane & 3) * 2 + h];

    // row argmin (over this warp's 64 cols, then quad-lanes, then smem across nwarps)
#pragma unroll
    for (int m2 = 0; m2 < 2; m2++)
#pragma unroll
        for (int rh = 0; rh < 2; rh++) {
            ull best = ~0ULL;
#pragma unroll
            for (int n2 = 0; n2 < 8; n2++)
#pragma unroll
                for (int h = 0; h < 2; h++) {
                    float d = fmaxf(naR[m2][rh] + nbC[n2][h] - 2.f * acc[m2][n2][rh * 2 + h], 0.f);
                    ull k = packkey(d, nw * 64 + n2 * 8 + (lane & 3) * 2 + h);
                    best = (k < best) ? k : best;
                }
            ull o = __shfl_xor_sync(0xffffffffu, best, 1); best = (o < best) ? o : best;
            o = __shfl_xor_sync(0xffffffffu, best, 2);     best = (o < best) ? o : best;
            if ((lane & 3) == 0)
                atomicMin(&rowKey[(mw * 2 + m2) * 16 + (lane >> 2) + rh * 8], best);
        }

    // col argmin (over this warp's 32 rows, reduce over 8 row-lanes, smem across mwarps)
#pragma unroll
    for (int n2 = 0; n2 < 8; n2++)
#pragma unroll
        for (int h = 0; h < 2; h++) {
            ull best = ~0ULL;
#pragma unroll
            for (int m2 = 0; m2 < 2; m2++)
#pragma unroll
                for (int rh = 0; rh < 2; rh++) {
                    float d = fmaxf(naR[m2][rh] + nbC[n2][h] - 2.f * acc[m2][n2][rh * 2 + h], 0.f);
                    ull k = packkey(d, mo + (mw * 2 + m2) * 16 + (lane >> 2) + rh * 8);
                    best = (k < best) ? k : best;
                }
            ull o = __shfl_xor_sync(0xffffffffu, best, 4);  best = (o < best) ? o : best;
            o = __shfl_xor_sync(0xffffffffu, best, 8);      best = (o < best) ? o : best;
            o = __shfl_xor_sync(0xffffffffu, best, 16);     best = (o < best) ? o : best;
            if (lane < 4)
                atomicMin(&colKey[nw * 64 + n2 * 8 + (lane & 3) * 2 + h], best);
        }
    __syncthreads();
    if (tid < 64) g_key_fg[(size_t)bb * LG + mo + tid] = rowKey[tid];  // block-local: direct store
    atomicMin(&g_key_fl[(size_t)bb * LL + tid], colKey[tid]);
}

// ================= grid-space NN + its top-k select, fused =================
__global__ void __launch_bounds__(256) gridnn_sel(const float* __restrict__ gg_in,
                                                  const float* __restrict__ gl_in) {
    int bb = blockIdx.x, dir = blockIdx.y;
    int Lin = dir ? LL : LG, Lc = dir ? LG : LL, Msel = dir ? ML : MG;
    const float* gin   = dir ? gl_in : gg_in;
    const float* gcand = dir ? gg_in : gl_in;
    ull* keyout = dir ? g_key_gl : g_key_gg;
    int* sel    = dir ? g_sel_gl : g_sel_gg;

    __shared__ float2 sc[LG];
    __shared__ ull sk[LG];
    __shared__ unsigned char flag[LG];
    const float2* gc = (const float2*)gcand + (size_t)bb * Lc;
    for (int i = threadIdx.x; i < Lc; i += blockDim.x) sc[i] = gc[i];
    __syncthreads();
    const float2* gi = (const float2*)gin + (size_t)bb * Lin;
    for (int l = threadIdx.x; l < Lin; l += blockDim.x) {
        float2 g = gi[l];
        float best = 3.4e38f; int bi = 0;
        for (int m = 0; m < Lc; m++) {
            float dx = g.x - sc[m].x, dy = g.y - sc[m].y;
            float d = dx * dx + dy * dy;
            if (d < best) { best = d; bi = m; }
        }
        ull k = packkey(best, bi);
        sk[l] = k;
        keyout[(size_t)bb * Lin + l] = k;
    }
    __syncthreads();
    for (int i = threadIdx.x; i < Lin; i += blockDim.x) {
        ull mine = sk[i]; int cnt = 0;
        for (int j = 0; j < Lin; j++) {
            ull o = sk[j];
            cnt += (o < mine) || (o == mine && j < i);
        }
        flag[i] = (cnt < Msel) ? 1 : 0;
    }
    __syncthreads();
    if (threadIdx.x == 0) {
        int p = 0;
        for (int i = 0; i < Lin && p < Msel; i++)
            if (flag[i]) sel[bb * Msel + (p++)] = i;
    }
}

// ================= feature-space top-k select =================
__global__ void __launch_bounds__(256) select_feat() {
    int bb = blockIdx.x, which = blockIdx.y;
    const ull* keys = which ? g_key_fl : g_key_fg;
    int L = which ? LL : LG, Msel = which ? ML : MG;
    int* sel = which ? g_sel_fl : g_sel_fg;

    __shared__ ull sk[LG];
    __shared__ unsigned char flag[LG];
    const ull* k = keys + (size_t)bb * L;
    for (int i = threadIdx.x; i < L; i += blockDim.x) sk[i] = k[i];
    __syncthreads();
    for (int i = threadIdx.x; i < L; i += blockDim.x) {
        ull mine = sk[i]; int cnt = 0;
        for (int j = 0; j < L; j++) {
            ull o = sk[j];
            cnt += (o < mine) || (o == mine && j < i);
        }
        flag[i] = (cnt < Msel) ? 1 : 0;
    }
    __syncthreads();
    if (threadIdx.x == 0) {
        int p = 0;
        for (int i = 0; i < L && p < Msel; i++)
            if (flag[i]) sel[bb * Msel + (p++)] = i;
    }
}

// ================= gathered MSE accumulation (all 4 sections) =================
__global__ void mse_kernel(const float* __restrict__ fG, const float* __restrict__ fL) {
    __shared__ float sh[8];
    int bb = blockIdx.x / 48;
    int r  = blockIdx.x % 48;
    int which, mi;
    if (r < MG)             { which = 0; mi = r; }
    else if (r < MG + ML)   { which = 1; mi = r - MG; }
    else if (r < 2*MG + ML) { which = 2; mi = r - MG - ML; }
    else                    { which = 3; mi = r - 2*MG - ML; }

    const float* fin; const float* fc; const int* sel; const ull* keys;
    int Lin, Lc, Msel, accIdx;
    if (which == 0)      { fin = fG; fc = fL; sel = g_sel_fg; keys = g_key_fg; Lin = LG; Lc = LL; Msel = MG; accIdx = 5; }
    else if (which == 1) { fin = fL; fc = fG; sel = g_sel_fl; keys = g_key_fl; Lin = LL; Lc = LG; Msel = ML; accIdx = 6; }
    else if (which == 2) { fin = fG; fc = fL; sel = g_sel_gg; keys = g_key_gg; Lin = LG; Lc = LL; Msel = MG; accIdx = 7; }
    else                 { fin = fL; fc = fG; sel = g_sel_gl; keys = g_key_gl; Lin = LL; Lc = LG; Msel = ML; accIdx = 8; }

    int row = sel[bb * Msel + mi];
    int cand = (int)(keys[(size_t)bb * Lin + row] & 0xffffffffULL);
    const float4* p = (const float4*)(fin + ((size_t)bb * Lin + row) * NC);
    const float4* q = (const float4*)(fc + ((size_t)bb * Lc + cand) * NC);
    float s = 0.f;
    for (int t = threadIdx.x; t < NC / 4; t += blockDim.x) {
        float4 x = p[t], y = q[t];
        float dx = x.x - y.x, dy = x.y - y.y, dz = x.z - y.z, dw = x.w - y.w;
        s += dx * dx + dy * dy + dz * dz + dw * dw;
    }
    s = block_reduce(s, sh);
    if (threadIdx.x == 0) atomicAdd(&g_acc[accIdx], s);
}

// ================= final combine =================
__global__ void final_kernel(float* __restrict__ out, int out_size) {
    __shared__ float sR[1024];
    __shared__ float rowsum[32];
    __shared__ float sh[8];
    __shared__ float covG[2];
    __shared__ float qsh;
    for (int mat = 0; mat < 2; mat++) {
        for (int t = threadIdx.x; t < 1024; t += blockDim.x) {
            float s = 0.f;
            for (int c = 0; c < 32; c++) s += g_Rp[mat][c][t];
            sR[t] = s;
        }
        __syncthreads();
        if (threadIdx.x < 32) {
            float s = 0.f;
            for (int k = 0; k < 32; k++) s += sR[threadIdx.x * 32 + k];
            rowsum[threadIdx.x] = s;
        }
        __syncthreads();
        if (threadIdx.x == 0) {
            float t = 0.f;
            for (int i = 0; i < 32; i++) t += rowsum[i];
            qsh = t * (1.f / 1024.f);
        }
        __syncthreads();
        float q = qsh;
        float part = 0.f;
        for (int t = threadIdx.x; t < 1024; t += blockDim.x) {
            int i = t >> 5, k = t & 31;
            float g = sR[t] - rowsum[i] * (1.f / 32.f) - rowsum[k] * (1.f / 32.f) + q;
            part += g * g;
        }
        float tot = block_reduce(part, sh);
        if (threadIdx.x == 0) covG[mat] = tot;
        __syncthreads();
    }
    if (threadIdx.x == 0) {
        float inv_g = g_acc[4] * (1.f / (32.f * 8192.f));
        float v = 0.5f * (g_acc[0] + g_acc[1]) * (1.f / 8192.f);
        float cov = ((covG[0] - g_acc[2]) + (covG[1] - g_acc[3])) * (1.f / (31.f * 31.f * 8192.f));
        float global_loss = 25.f * inv_g + 25.f * v + 1.f * cov;
        float mfg = g_acc[5] * (1.f / (32.f * MG * NC));
        float mfl = g_acc[6] * (1.f / (32.f * ML * NC));
        float mgg = g_acc[7] * (1.f / (32.f * MG * NC));
        float mgl = g_acc[8] * (1.f / (32.f * ML * NC));
        float local_loss = 25.f * (0.5f * (mfg + mfl) + 0.5f * (mgg + mgl));
        float res = 0.25f * global_loss + 0.75f * local_loss;
        for (int i = 0; i < out_size; i++) out[i] = res;
    }
}

extern "C" void kernel_launch(void* const* d_in, const int* in_sizes, int n_in,
                              void* d_out, int out_size) {
    (void)in_sizes; (void)n_in;
    const float* zg = (const float*)d_in[0];   // (32, 8192)
    const float* zl = (const float*)d_in[1];   // (32, 8192)
    const float* fg = (const float*)d_in[2];   // (32, 576, 512)
    const float* fl = (const float*)d_in[3];   // (32, 256, 512)
    const float* gg = (const float*)d_in[4];   // (32, 576, 2)
    const float* gl = (const float*)d_in[5];   // (32, 256, 2)
    float* out = (float*)d_out;

    fused_pre<<<225, 256>>>(zg, zl, fg, fl);

    {
        dim3 grid(LG / 64, NB);
        cdist_mma<<<grid, 256>>>(fg, fl);
    }
    {
        dim3 grid(NB, 2);
        gridnn_sel<<<grid, 256>>>(gg, gl);
    }
    {
        dim3 grid(NB, 2);
        select_feat<<<grid, 256>>>();
    }
    mse_kernel<<<NB * 48, 128>>>(fg, fl);
    final_kernel<<<1, 256>>>(out, out_size);
}

// round 5
// speedup vs baseline: 2.7045x; 1.4672x over previous
#include <cuda_runtime.h>

typedef unsigned long long ull;
typedef unsigned int u32;

#define NB 32
#define LG 576
#define LL 256
#define NC 512
#define ND 8192
#define MG 20
#define ML 4

// ---------------- device scratch (no allocations allowed) ----------------
__device__ ull   g_key_fg[NB * LG];
__device__ ull   g_key_fl[NB * LL];
__device__ ull   g_key_gg[NB * LG];
__device__ ull   g_key_gl[NB * LL];
__device__ int   g_sel_fg[NB * MG];
__device__ int   g_sel_fl[NB * ML];
__device__ int   g_sel_gg[NB * MG];
__device__ int   g_sel_gl[NB * ML];
__device__ float g_normg[NB * LG];
__device__ float g_norml[NB * LL];
__device__ float g_Rp[2][32][1024];
__device__ float g_acc[16];
// acc: 0 var_a, 1 var_b, 2 sum s_j^2 a, 3 sum s_j^2 b, 4 inv-sum,
//      5 mse_fg, 6 mse_fl, 7 mse_gg, 8 mse_gl

__device__ __forceinline__ ull packkey(float d, int i) {
    return (((ull)__float_as_uint(d)) << 32) | (unsigned)i;
}

__device__ __forceinline__ u32 f2tf(float x) {
    u32 r; asm("cvt.rna.tf32.f32 %0, %1;" : "=r"(r) : "f"(x)); return r;
}

#define MMA_TF32(C, A, B0, B1)                                              \
    asm volatile("mma.sync.aligned.m16n8k8.row.col.f32.tf32.tf32.f32 "      \
                 "{%0,%1,%2,%3}, {%4,%5,%6,%7}, {%8,%9}, {%0,%1,%2,%3};"    \
                 : "+f"((C)[0]), "+f"((C)[1]), "+f"((C)[2]), "+f"((C)[3])   \
                 : "r"((A)[0]), "r"((A)[1]), "r"((A)[2]), "r"((A)[3]),      \
                   "r"(B0), "r"(B1))

__device__ float block_reduce(float v, float* sh) {
    __syncthreads();
    int lane = threadIdx.x & 31, wid = threadIdx.x >> 5;
#pragma unroll
    for (int o = 16; o; o >>= 1) v += __shfl_down_sync(0xffffffffu, v, o);
    if (lane == 0) sh[wid] = v;
    __syncthreads();
    float r = 0.f;
    if (wid == 0) {
        int nw = (blockDim.x + 31) >> 5;
        r = (lane < nw) ? sh[lane] : 0.f;
#pragma unroll
        for (int o = 16; o; o >>= 1) r += __shfl_down_sync(0xffffffffu, r, o);
    }
    return r;  // valid on thread 0
}

// ================= fused pre-kernel =================
// blocks 0..31: per-dim VICReg stats; 32..95: split-K gram; 96..127: fl norms;
// 128..223: fg norms; 224: init; 225..288: grid-space NN (64 = 32 batches x 2 dirs).
__global__ void __launch_bounds__(256) fused_pre(const float* __restrict__ za,
                                                 const float* __restrict__ zb,
                                                 const float* __restrict__ fg,
                                                 const float* __restrict__ fl,
                                                 const float* __restrict__ gg_in,
                                                 const float* __restrict__ gl_in) {
    __shared__ float sh[8];
    int blk = blockIdx.x, tid = threadIdx.x;
    if (blk < 32) {
        int j = blk * 256 + tid;
        float sa = 0, sqa = 0, sb = 0, sqb = 0, sd = 0;
#pragma unroll 8
        for (int i = 0; i < 32; i++) {
            float x = za[(size_t)i * ND + j], y = zb[(size_t)i * ND + j];
            sa += x; sqa += x * x; sb += y; sqb += y * y;
            float df = x - y; sd += df * df;
        }
        float s_a = sqa - sa * sa * (1.f / 32.f);
        float s_b = sqb - sb * sb * (1.f / 32.f);
        float va = fmaxf(0.f, 1.f - sqrtf(s_a * (1.f / 31.f) + 1e-4f));
        float vb = fmaxf(0.f, 1.f - sqrtf(s_b * (1.f / 31.f) + 1e-4f));
        float r;
        r = block_reduce(va, sh);        if (tid == 0) atomicAdd(&g_acc[0], r);
        r = block_reduce(vb, sh);        if (tid == 0) atomicAdd(&g_acc[1], r);
        r = block_reduce(s_a * s_a, sh); if (tid == 0) atomicAdd(&g_acc[2], r);
        r = block_reduce(s_b * s_b, sh); if (tid == 0) atomicAdd(&g_acc[3], r);
        r = block_reduce(sd, sh);        if (tid == 0) atomicAdd(&g_acc[4], r);
    } else if (blk < 96) {
        __shared__ float s[32][257];
        int idx = blk - 32;
        int mat = idx >> 5, chunk = idx & 31;
        int d0 = chunk * 256;
        const float* z = mat ? zb : za;
        for (int i = tid; i < 2048; i += 256) {
            int row = i >> 6, c4 = i & 63;
            float4 v = *(const float4*)(z + (size_t)row * ND + d0 + c4 * 4);
            s[row][c4 * 4 + 0] = v.x; s[row][c4 * 4 + 1] = v.y;
            s[row][c4 * 4 + 2] = v.z; s[row][c4 * 4 + 3] = v.w;
        }
        __syncthreads();
        int ia = tid >> 3, kb = (tid & 7) * 4;
        float c[4] = {};
        for (int d = 0; d < 256; d++) {
            float av = s[ia][d];
#pragma unroll
            for (int j = 0; j < 4; j++) c[j] = fmaf(av, s[kb + j][d], c[j]);
        }
#pragma unroll
        for (int j = 0; j < 4; j++) g_Rp[mat][chunk][ia * 32 + kb + j] = c[j];
    } else if (blk < 224) {
        const float* src; float* dst; int rows, w, wtot;
        if (blk < 128) { src = fl; dst = g_norml; rows = NB * LL; w = (blk - 96) * 8 + (tid >> 5); wtot = 32 * 8; }
        else           { src = fg; dst = g_normg; rows = NB * LG; w = (blk - 128) * 8 + (tid >> 5); wtot = 96 * 8; }
        int lane = tid & 31;
        for (int row = w; row < rows; row += wtot) {
            const float4* p = (const float4*)(src + (size_t)row * NC);
            float s = 0.f;
#pragma unroll
            for (int i = 0; i < 4; i++) {
                float4 v = p[lane + i * 32];
                s += v.x * v.x + v.y * v.y + v.z * v.z + v.w * v.w;
            }
#pragma unroll
            for (int o = 16; o; o >>= 1) s += __shfl_down_sync(0xffffffffu, s, o);
            if (lane == 0) dst[row] = s;
        }
    } else if (blk == 224) {
        if (tid < 16) g_acc[tid] = 0.f;
        for (int i = tid; i < NB * LL; i += 256) g_key_fl[i] = ~0ULL;
    } else {
        // grid-space NN (no select here)
        int idx = blk - 225;
        int bb = idx >> 1, dir = idx & 1;
        int Lin = dir ? LL : LG, Lc = dir ? LG : LL;
        const float* gin   = dir ? gl_in : gg_in;
        const float* gcand = dir ? gg_in : gl_in;
        ull* keyout = dir ? g_key_gl : g_key_gg;
        __shared__ float2 sc[LG];
        const float2* gc = (const float2*)gcand + (size_t)bb * Lc;
        for (int i = tid; i < Lc; i += 256) sc[i] = gc[i];
        __syncthreads();
        const float2* gi = (const float2*)gin + (size_t)bb * Lin;
        for (int l = tid; l < Lin; l += 256) {
            float2 g = gi[l];
            float best = 3.4e38f; int bi = 0;
            for (int m = 0; m < Lc; m++) {
                float dx = g.x - sc[m].x, dy = g.y - sc[m].y;
                float d = dx * dx + dy * dy;
                if (d < best) { best = d; bi = m; }
            }
            keyout[(size_t)bb * Lin + l] = packkey(best, bi);
        }
    }
}

// ================= tensor-core cdist^2 + row/col argmin =================
__global__ void __launch_bounds__(256, 2) cdist_mma(const float* __restrict__ Ag,
                                                    const float* __restrict__ Bg) {
    int bb = blockIdx.y;
    int mo = blockIdx.x * 64;
    const float* A = Ag + (size_t)bb * LG * NC;
    const float* B = Bg + (size_t)bb * LL * NC;

    __shared__ u32 As[4 * 4 * 4 * 32];    // [ks][mfrag][reg][lane^swz]
    __shared__ u32 Bs[4 * 32 * 2 * 32];   // [ks][nfrag][reg][lane^swz]
    __shared__ ull rowKey[64];
    __shared__ ull colKey[LL];

    int tid = threadIdx.x, lane = tid & 31, warp = tid >> 5;
    int mw = warp >> 2, nw = warp & 3;
    if (tid < 64) rowKey[tid] = ~0ULL;
    colKey[tid] = ~0ULL;

    float acc[2][8][4];
#pragma unroll
    for (int i = 0; i < 2; i++)
#pragma unroll
        for (int j = 0; j < 8; j++)
#pragma unroll
            for (int k = 0; k < 4; k++) acc[i][j][k] = 0.f;

    for (int ch = 0; ch < 16; ch++) {
        int koff = ch * 32;
#pragma unroll
        for (int i = 0; i < 2; i++) {
            int f = tid + i * 256;
            int r = f >> 3, c0 = (f & 7) * 4;
            float4 v = *(const float4*)(A + (size_t)(mo + r) * NC + koff + c0);
            int ks = c0 >> 3, half = (c0 & 7) >> 2;
            int reg = half * 2 + ((r & 15) >> 3);
            int lb = (((r & 7) * 4) ^ (ks << 2) ^ (half << 4));
            uint4 o = make_uint4(f2tf(v.x), f2tf(v.y), f2tf(v.z), f2tf(v.w));
            *(uint4*)&As[(((ks * 4 + (r >> 4)) * 4 + reg) * 32) + lb] = o;
        }
#pragma unroll
        for (int i = 0; i < 8; i++) {
            int f = tid + i * 256;
            int n = f >> 3, c0 = (f & 7) * 4;
            float4 v = *(const float4*)(B + (size_t)n * NC + koff + c0);
            int ks = c0 >> 3, reg = (c0 & 7) >> 2;
            int lb = (((n & 7) * 4) ^ (ks << 2) ^ (reg << 4));
            uint4 o = make_uint4(f2tf(v.x), f2tf(v.y), f2tf(v.z), f2tf(v.w));
            *(uint4*)&Bs[(((ks * 32 + (n >> 3)) * 2 + reg) * 32) + lb] = o;
        }
        __syncthreads();
#pragma unroll
        for (int ks = 0; ks < 4; ks++) {
            u32 a[2][4];
#pragma unroll
            for (int m2 = 0; m2 < 2; m2++) {
                int mf = mw * 2 + m2;
                int base = ((ks * 4 + mf) * 4) * 32;
#pragma unroll
                for (int rg = 0; rg < 4; rg++)
                    a[m2][rg] = As[base + rg * 32 + (lane ^ (ks << 2) ^ ((rg >> 1) << 4))];
            }
#pragma unroll
            for (int n2 = 0; n2 < 8; n2++) {
                int nf = nw * 8 + n2;
                u32 b0 = Bs[((ks * 32 + nf) * 2 + 0) * 32 + (lane ^ (ks << 2))];
                u32 b1 = Bs[((ks * 32 + nf) * 2 + 1) * 32 + (lane ^ (ks << 2) ^ 16)];
                MMA_TF32(acc[0][n2], a[0], b0, b1);
                MMA_TF32(acc[1][n2], a[1], b0, b1);
            }
        }
        __syncthreads();
    }

    // ---- epilogue: d2 = na + nb - 2*dot, packed-key argmins ----
    float naR[2][2], nbC[8][2];
#pragma unroll
    for (int m2 = 0; m2 < 2; m2++)
#pragma unroll
        for (int rh = 0; rh < 2; rh++)
            naR[m2][rh] = g_normg[bb * LG + mo + (mw * 2 + m2) * 16 + (lane >> 2) + rh * 8];
#pragma unroll
    for (int n2 = 0; n2 < 8; n2++)
#pragma unroll
        for (int h = 0; h < 2; h++)
            nbC[n2][h] = g_norml[bb * LL + nw * 64 + n2 * 8 + (lane & 3) * 2 + h];

#pragma unroll
    for (int m2 = 0; m2 < 2; m2++)
#pragma unroll
        for (int rh = 0; rh < 2; rh++) {
            ull best = ~0ULL;
#pragma unroll
            for (int n2 = 0; n2 < 8; n2++)
#pragma unroll
                for (int h = 0; h < 2; h++) {
                    float d = fmaxf(naR[m2][rh] + nbC[n2][h] - 2.f * acc[m2][n2][rh * 2 + h], 0.f);
                    ull k = packkey(d, nw * 64 + n2 * 8 + (lane & 3) * 2 + h);
                    best = (k < best) ? k : best;
                }
            ull o = __shfl_xor_sync(0xffffffffu, best, 1); best = (o < best) ? o : best;
            o = __shfl_xor_sync(0xffffffffu, best, 2);     best = (o < best) ? o : best;
            if ((lane & 3) == 0)
                atomicMin(&rowKey[(mw * 2 + m2) * 16 + (lane >> 2) + rh * 8], best);
        }

#pragma unroll
    for (int n2 = 0; n2 < 8; n2++)
#pragma unroll
        for (int h = 0; h < 2; h++) {
            ull best = ~0ULL;
#pragma unroll
            for (int m2 = 0; m2 < 2; m2++)
#pragma unroll
                for (int rh = 0; rh < 2; rh++) {
                    float d = fmaxf(naR[m2][rh] + nbC[n2][h] - 2.f * acc[m2][n2][rh * 2 + h], 0.f);
                    ull k = packkey(d, mo + (mw * 2 + m2) * 16 + (lane >> 2) + rh * 8);
                    best = (k < best) ? k : best;
                }
            ull o = __shfl_xor_sync(0xffffffffu, best, 4);  best = (o < best) ? o : best;
            o = __shfl_xor_sync(0xffffffffu, best, 8);      best = (o < best) ? o : best;
            o = __shfl_xor_sync(0xffffffffu, best, 16);     best = (o < best) ? o : best;
            if (lane < 4)
                atomicMin(&colKey[nw * 64 + n2 * 8 + (lane & 3) * 2 + h], best);
        }
    __syncthreads();
    if (tid < 64) g_key_fg[(size_t)bb * LG + mo + tid] = rowKey[tid];
    atomicMin(&g_key_fl[(size_t)bb * LL + tid], colKey[tid]);
}

// ================= unified top-k selection (all 4 sections) =================
// grid (NB, 4), 576 threads: 1 thread per candidate row, unrolled rank count.
__global__ void __launch_bounds__(576) select_all() {
    int bb = blockIdx.x, which = blockIdx.y;
    const ull* keys; int L, Msel; int* sel;
    if (which == 0)      { keys = g_key_fg; L = LG; Msel = MG; sel = g_sel_fg; }
    else if (which == 1) { keys = g_key_fl; L = LL; Msel = ML; sel = g_sel_fl; }
    else if (which == 2) { keys = g_key_gg; L = LG; Msel = MG; sel = g_sel_gg; }
    else                 { keys = g_key_gl; L = LL; Msel = ML; sel = g_sel_gl; }

    __shared__ ull sk[LG];
    __shared__ unsigned char flag[LG];
    int tid = threadIdx.x;
    if (tid < L) sk[tid] = keys[(size_t)bb * L + tid];
    __syncthreads();
    if (tid < L) {
        ull mine = sk[tid];
        int cnt = 0;
#pragma unroll 8
        for (int j = 0; j < L; j++) {
            ull o = sk[j];
            cnt += (o < mine) || (o == mine && j < tid);
        }
        flag[tid] = (cnt < Msel) ? 1 : 0;
    }
    __syncthreads();
    if (tid == 0) {
        int p = 0;
        for (int i = 0; i < L && p < Msel; i++)
            if (flag[i]) sel[bb * Msel + (p++)] = i;
    }
}

// ================= gathered MSE accumulation (all 4 sections) =================
__global__ void mse_kernel(const float* __restrict__ fG, const float* __restrict__ fL) {
    __shared__ float sh[8];
    int bb = blockIdx.x / 48;
    int r  = blockIdx.x % 48;
    int which, mi;
    if (r < MG)             { which = 0; mi = r; }
    else if (r < MG + ML)   { which = 1; mi = r - MG; }
    else if (r < 2*MG + ML) { which = 2; mi = r - MG - ML; }
    else                    { which = 3; mi = r - 2*MG - ML; }

    const float* fin; const float* fc; const int* sel; const ull* keys;
    int Lin, Lc, Msel, accIdx;
    if (which == 0)      { fin = fG; fc = fL; sel = g_sel_fg; keys = g_key_fg; Lin = LG; Lc = LL; Msel = MG; accIdx = 5; }
    else if (which == 1) { fin = fL; fc = fG; sel = g_sel_fl; keys = g_key_fl; Lin = LL; Lc = LG; Msel = ML; accIdx = 6; }
    else if (which == 2) { fin = fG; fc = fL; sel = g_sel_gg; keys = g_key_gg; Lin = LG; Lc = LL; Msel = MG; accIdx = 7; }
    else                 { fin = fL; fc = fG; sel = g_sel_gl; keys = g_key_gl; Lin = LL; Lc = LG; Msel = ML; accIdx = 8; }

    int row = sel[bb * Msel + mi];
    int cand = (int)(keys[(size_t)bb * Lin + row] & 0xffffffffULL);
    const float4* p = (const float4*)(fin + ((size_t)bb * Lin + row) * NC);
    const float4* q = (const float4*)(fc + ((size_t)bb * Lc + cand) * NC);
    float s = 0.f;
    for (int t = threadIdx.x; t < NC / 4; t += blockDim.x) {
        float4 x = p[t], y = q[t];
        float dx = x.x - y.x, dy = x.y - y.y, dz = x.z - y.z, dw = x.w - y.w;
        s += dx * dx + dy * dy + dz * dz + dw * dw;
    }
    s = block_reduce(s, sh);
    if (threadIdx.x == 0) atomicAdd(&g_acc[accIdx], s);
}

// ================= final combine =================
__global__ void final_kernel(float* __restrict__ out, int out_size) {
    __shared__ float sR[1024];
    __shared__ float rowsum[32];
    __shared__ float sh[8];
    __shared__ float covG[2];
    __shared__ float qsh;
    for (int mat = 0; mat < 2; mat++) {
        for (int t = threadIdx.x; t < 1024; t += blockDim.x) {
            float s = 0.f;
            for (int c = 0; c < 32; c++) s += g_Rp[mat][c][t];
            sR[t] = s;
        }
        __syncthreads();
        if (threadIdx.x < 32) {
            float s = 0.f;
            for (int k = 0; k < 32; k++) s += sR[threadIdx.x * 32 + k];
            rowsum[threadIdx.x] = s;
        }
        __syncthreads();
        if (threadIdx.x == 0) {
            float t = 0.f;
            for (int i = 0; i < 32; i++) t += rowsum[i];
            qsh = t * (1.f / 1024.f);
        }
        __syncthreads();
        float q = qsh;
        float part = 0.f;
        for (int t = threadIdx.x; t < 1024; t += blockDim.x) {
            int i = t >> 5, k = t & 31;
            float g = sR[t] - rowsum[i] * (1.f / 32.f) - rowsum[k] * (1.f / 32.f) + q;
            part += g * g;
        }
        float tot = block_reduce(part, sh);
        if (threadIdx.x == 0) covG[mat] = tot;
        __syncthreads();
    }
    if (threadIdx.x == 0) {
        float inv_g = g_acc[4] * (1.f / (32.f * 8192.f));
        float v = 0.5f * (g_acc[0] + g_acc[1]) * (1.f / 8192.f);
        float cov = ((covG[0] - g_acc[2]) + (covG[1] - g_acc[3])) * (1.f / (31.f * 31.f * 8192.f));
        float global_loss = 25.f * inv_g + 25.f * v + 1.f * cov;
        float mfg = g_acc[5] * (1.f / (32.f * MG * NC));
        float mfl = g_acc[6] * (1.f / (32.f * ML * NC));
        float mgg = g_acc[7] * (1.f / (32.f * MG * NC));
        float mgl = g_acc[8] * (1.f / (32.f * ML * NC));
        float local_loss = 25.f * (0.5f * (mfg + mfl) + 0.5f * (mgg + mgl));
        float res = 0.25f * global_loss + 0.75f * local_loss;
        for (int i = 0; i < out_size; i++) out[i] = res;
    }
}

extern "C" void kernel_launch(void* const* d_in, const int* in_sizes, int n_in,
                              void* d_out, int out_size) {
    (void)in_sizes; (void)n_in;
    const float* zg = (const float*)d_in[0];   // (32, 8192)
    const float* zl = (const float*)d_in[1];   // (32, 8192)
    const float* fg = (const float*)d_in[2];   // (32, 576, 512)
    const float* fl = (const float*)d_in[3];   // (32, 256, 512)
    const float* gg = (const float*)d_in[4];   // (32, 576, 2)
    const float* gl = (const float*)d_in[5];   // (32, 256, 2)
    float* out = (float*)d_out;

    fused_pre<<<289, 256>>>(zg, zl, fg, fl, gg, gl);

    {
        dim3 grid(LG / 64, NB);
        cdist_mma<<<grid, 256>>>(fg, fl);
    }
    {
        dim3 grid(NB, 4);
        select_all<<<grid, 576>>>();
    }
    mse_kernel<<<NB * 48, 128>>>(fg, fl);
    final_kernel<<<1, 256>>>(out, out_size);
}

// round 6
// speedup vs baseline: 3.0717x; 1.1358x over previous
#include <cuda_runtime.h>

typedef unsigned long long ull;
typedef unsigned int u32;

#define NB 32
#define LG 576
#define LL 256
#define NC 512
#define ND 8192
#define MG 20
#define ML 4

// ---------------- device scratch (no allocations allowed) ----------------
__device__ ull   g_key_fg[NB * LG];
__device__ ull   g_key_fl[NB * LL];
__device__ ull   g_key_gg[NB * LG];
__device__ ull   g_key_gl[NB * LL];
__device__ float g_normg[NB * LG];
__device__ float g_norml[NB * LL];
__device__ float g_Rp[2][32][1024];
__device__ float g_acc[16];
// acc: 0 var_a, 1 var_b, 2 sum s_j^2 a, 3 sum s_j^2 b, 4 inv-sum,
//      5 mse_fg, 6 mse_fl, 7 mse_gg, 8 mse_gl

__device__ __forceinline__ ull packkey(float d, int i) {
    return (((ull)__float_as_uint(d)) << 32) | (unsigned)i;
}

#define MMA_TF32(C, A, B0, B1)                                              \
    asm volatile("mma.sync.aligned.m16n8k8.row.col.f32.tf32.tf32.f32 "      \
                 "{%0,%1,%2,%3}, {%4,%5,%6,%7}, {%8,%9}, {%0,%1,%2,%3};"    \
                 : "+f"((C)[0]), "+f"((C)[1]), "+f"((C)[2]), "+f"((C)[3])   \
                 : "r"((A)[0]), "r"((A)[1]), "r"((A)[2]), "r"((A)[3]),      \
                   "r"(B0), "r"(B1))

__device__ __forceinline__ void cpa16(u32 dst, const void* src) {
    asm volatile("cp.async.ca.shared.global [%0], [%1], 16;" :: "r"(dst), "l"(src));
}
#define CP_COMMIT() asm volatile("cp.async.commit_group;" ::: "memory")

__device__ float block_reduce(float v, float* sh) {
    __syncthreads();
    int lane = threadIdx.x & 31, wid = threadIdx.x >> 5;
#pragma unroll
    for (int o = 16; o; o >>= 1) v += __shfl_down_sync(0xffffffffu, v, o);
    if (lane == 0) sh[wid] = v;
    __syncthreads();
    float r = 0.f;
    if (wid == 0) {
        int nw = (blockDim.x + 31) >> 5;
        r = (lane < nw) ? sh[lane] : 0.f;
#pragma unroll
        for (int o = 16; o; o >>= 1) r += __shfl_down_sync(0xffffffffu, r, o);
    }
    return r;  // valid on thread 0
}

// ================= fused pre-kernel =================
// blocks 0..31: per-dim VICReg stats; 32..95: split-K gram; 96..127: fl norms;
// 128..223: fg norms; 224: init; 225..288: grid-space NN (32 batches x 2 dirs).
__global__ void __launch_bounds__(256) fused_pre(const float* __restrict__ za,
                                                 const float* __restrict__ zb,
                                                 const float* __restrict__ fg,
                                                 const float* __restrict__ fl,
                                                 const float* __restrict__ gg_in,
                                                 const float* __restrict__ gl_in) {
    __shared__ float sh[8];
    int blk = blockIdx.x, tid = threadIdx.x;
    if (blk < 32) {
        int j = blk * 256 + tid;
        float sa = 0, sqa = 0, sb = 0, sqb = 0, sd = 0;
#pragma unroll 8
        for (int i = 0; i < 32; i++) {
            float x = za[(size_t)i * ND + j], y = zb[(size_t)i * ND + j];
            sa += x; sqa += x * x; sb += y; sqb += y * y;
            float df = x - y; sd += df * df;
        }
        float s_a = sqa - sa * sa * (1.f / 32.f);
        float s_b = sqb - sb * sb * (1.f / 32.f);
        float va = fmaxf(0.f, 1.f - sqrtf(s_a * (1.f / 31.f) + 1e-4f));
        float vb = fmaxf(0.f, 1.f - sqrtf(s_b * (1.f / 31.f) + 1e-4f));
        float r;
        r = block_reduce(va, sh);        if (tid == 0) atomicAdd(&g_acc[0], r);
        r = block_reduce(vb, sh);        if (tid == 0) atomicAdd(&g_acc[1], r);
        r = block_reduce(s_a * s_a, sh); if (tid == 0) atomicAdd(&g_acc[2], r);
        r = block_reduce(s_b * s_b, sh); if (tid == 0) atomicAdd(&g_acc[3], r);
        r = block_reduce(sd, sh);        if (tid == 0) atomicAdd(&g_acc[4], r);
    } else if (blk < 96) {
        __shared__ float s[32][257];
        int idx = blk - 32;
        int mat = idx >> 5, chunk = idx & 31;
        int d0 = chunk * 256;
        const float* z = mat ? zb : za;
        for (int i = tid; i < 2048; i += 256) {
            int row = i >> 6, c4 = i & 63;
            float4 v = *(const float4*)(z + (size_t)row * ND + d0 + c4 * 4);
            s[row][c4 * 4 + 0] = v.x; s[row][c4 * 4 + 1] = v.y;
            s[row][c4 * 4 + 2] = v.z; s[row][c4 * 4 + 3] = v.w;
        }
        __syncthreads();
        int ia = tid >> 3, kb = (tid & 7) * 4;
        float c[4] = {};
        for (int d = 0; d < 256; d++) {
            float av = s[ia][d];
#pragma unroll
            for (int j = 0; j < 4; j++) c[j] = fmaf(av, s[kb + j][d], c[j]);
        }
#pragma unroll
        for (int j = 0; j < 4; j++) g_Rp[mat][chunk][ia * 32 + kb + j] = c[j];
    } else if (blk < 224) {
        const float* src; float* dst; int rows, w, wtot;
        if (blk < 128) { src = fl; dst = g_norml; rows = NB * LL; w = (blk - 96) * 8 + (tid >> 5); wtot = 32 * 8; }
        else           { src = fg; dst = g_normg; rows = NB * LG; w = (blk - 128) * 8 + (tid >> 5); wtot = 96 * 8; }
        int lane = tid & 31;
        for (int row = w; row < rows; row += wtot) {
            const float4* p = (const float4*)(src + (size_t)row * NC);
            float s = 0.f;
#pragma unroll
            for (int i = 0; i < 4; i++) {
                float4 v = p[lane + i * 32];
                s += v.x * v.x + v.y * v.y + v.z * v.z + v.w * v.w;
            }
#pragma unroll
            for (int o = 16; o; o >>= 1) s += __shfl_down_sync(0xffffffffu, s, o);
            if (lane == 0) dst[row] = s;
        }
    } else if (blk == 224) {
        if (tid < 16) g_acc[tid] = 0.f;
        for (int i = tid; i < NB * LL; i += 256) g_key_fl[i] = ~0ULL;
    } else {
        // grid-space NN (select happens later in selmse)
        int idx = blk - 225;
        int bb = idx >> 1, dir = idx & 1;
        int Lin = dir ? LL : LG, Lc = dir ? LG : LL;
        const float* gin   = dir ? gl_in : gg_in;
        const float* gcand = dir ? gg_in : gl_in;
        ull* keyout = dir ? g_key_gl : g_key_gg;
        __shared__ float2 sc[LG];
        const float2* gc = (const float2*)gcand + (size_t)bb * Lc;
        for (int i = tid; i < Lc; i += 256) sc[i] = gc[i];
        __syncthreads();
        const float2* gi = (const float2*)gin + (size_t)bb * Lin;
        for (int l = tid; l < Lin; l += 256) {
            float2 g = gi[l];
            float best = 3.4e38f; int bi = 0;
            for (int m = 0; m < Lc; m++) {
                float dx = g.x - sc[m].x, dy = g.y - sc[m].y;
                float d = dx * dx + dy * dy;
                if (d < best) { best = d; bi = m; }
            }
            keyout[(size_t)bb * Lin + l] = packkey(best, bi);
        }
    }
}

// ================= tensor-core cdist^2 + row/col argmin =================
// cp.async double-buffered, K-chunk 16, raw f32 bits as tf32 (HW truncates).
__global__ void __launch_bounds__(256, 3) cdist_mma(const float* __restrict__ Ag,
                                                    const float* __restrict__ Bg) {
    int bb = blockIdx.y;
    int mo = blockIdx.x * 64;
    const float* A = Ag + (size_t)bb * LG * NC;
    const float* B = Bg + (size_t)bb * LL * NC;

    __shared__ u32 As[2][2 * 4 * 4 * 32];    // [stage][ks][mfrag][reg][lane^swz]  (4 KB/stage)
    __shared__ u32 Bs[2][2 * 32 * 2 * 32];   // [stage][ks][nfrag][reg][lane^swz] (16 KB/stage)
    __shared__ ull rowKey[64];
    __shared__ ull colKey[LL];

    int tid = threadIdx.x, lane = tid & 31, warp = tid >> 5;
    int mw = warp >> 2, nw = warp & 3;
    if (tid < 64) rowKey[tid] = ~0ULL;
    colKey[tid] = ~0ULL;

    // per-thread cp.async roles
    int ar = tid >> 2, ac0 = (tid & 3) * 4;                    // A: 64 rows x 16 k
    int aks = ac0 >> 3, ahalf = (ac0 & 7) >> 2;
    int areg = ahalf * 2 + ((ar & 15) >> 3);
    int alb = ((ar & 7) * 4) ^ (aks << 2) ^ (ahalf << 4);
    int aoff = (((aks * 4 + (ar >> 4)) * 4 + areg) * 32) + alb;
    const float* aptr = A + (size_t)(mo + ar) * NC + ac0;

    u32 asb[2], bsb[2];
    asb[0] = (u32)__cvta_generic_to_shared(&As[0][0]);
    asb[1] = (u32)__cvta_generic_to_shared(&As[1][0]);
    bsb[0] = (u32)__cvta_generic_to_shared(&Bs[0][0]);
    bsb[1] = (u32)__cvta_generic_to_shared(&Bs[1][0]);

    int boff[4]; const float* bptr[4];
#pragma unroll
    for (int i = 0; i < 4; i++) {
        int f = tid + i * 256;
        int n = f >> 2, c0 = (f & 3) * 4;
        int ks = c0 >> 3, reg = (c0 & 7) >> 2;
        int lb = ((n & 7) * 4) ^ (ks << 2) ^ (reg << 4);
        boff[i] = (((ks * 32 + (n >> 3)) * 2 + reg) * 32) + lb;
        bptr[i] = B + (size_t)n * NC + c0;
    }

#define LOAD_STAGE(CH, ST)                                                   \
    do {                                                                     \
        int koff_ = (CH) * 16;                                               \
        cpa16(asb[ST] + aoff * 4, aptr + koff_);                             \
        _Pragma("unroll")                                                    \
        for (int i_ = 0; i_ < 4; i_++)                                       \
            cpa16(bsb[ST] + boff[i_] * 4, bptr[i_] + koff_);                 \
        CP_COMMIT();                                                         \
    } while (0)

    float acc[2][8][4];
#pragma unroll
    for (int i = 0; i < 2; i++)
#pragma unroll
        for (int j = 0; j < 8; j++)
#pragma unroll
            for (int k = 0; k < 4; k++) acc[i][j][k] = 0.f;

    LOAD_STAGE(0, 0);
    LOAD_STAGE(1, 1);

    for (int ch = 0; ch < 32; ch++) {
        if (ch < 31) asm volatile("cp.async.wait_group 1;" ::: "memory");
        else         asm volatile("cp.async.wait_group 0;" ::: "memory");
        __syncthreads();
        int st = ch & 1;
        const u32* as = As[st];
        const u32* bs = Bs[st];
#pragma unroll
        for (int ks = 0; ks < 2; ks++) {
            u32 a[2][4];
#pragma unroll
            for (int m2 = 0; m2 < 2; m2++) {
                int mf = mw * 2 + m2;
                int base = ((ks * 4 + mf) * 4) * 32;
#pragma unroll
                for (int rg = 0; rg < 4; rg++)
                    a[m2][rg] = as[base + rg * 32 + (lane ^ (ks << 2) ^ ((rg >> 1) << 4))];
            }
#pragma unroll
            for (int n2 = 0; n2 < 8; n2++) {
                int nf = nw * 8 + n2;
                u32 b0 = bs[((ks * 32 + nf) * 2 + 0) * 32 + (lane ^ (ks << 2))];
                u32 b1 = bs[((ks * 32 + nf) * 2 + 1) * 32 + (lane ^ (ks << 2) ^ 16)];
                MMA_TF32(acc[0][n2], a[0], b0, b1);
                MMA_TF32(acc[1][n2], a[1], b0, b1);
            }
        }
        __syncthreads();
        if (ch + 2 < 32) LOAD_STAGE(ch + 2, st);
    }

    // ---- epilogue: d2 = na + nb - 2*dot, packed-key argmins ----
    float naR[2][2], nbC[8][2];
#pragma unroll
    for (int m2 = 0; m2 < 2; m2++)
#pragma unroll
        for (int rh = 0; rh < 2; rh++)
            naR[m2][rh] = g_normg[bb * LG + mo + (mw * 2 + m2) * 16 + (lane >> 2) + rh * 8];
#pragma unroll
    for (int n2 = 0; n2 < 8; n2++)
#pragma unroll
        for (int h = 0; h < 2; h++)
            nbC[n2][h] = g_norml[bb * LL + nw * 64 + n2 * 8 + (lane & 3) * 2 + h];

#pragma unroll
    for (int m2 = 0; m2 < 2; m2++)
#pragma unroll
        for (int rh = 0; rh < 2; rh++) {
            ull best = ~0ULL;
#pragma unroll
            for (int n2 = 0; n2 < 8; n2++)
#pragma unroll
                for (int h = 0; h < 2; h++) {
                    float d = fmaxf(naR[m2][rh] + nbC[n2][h] - 2.f * acc[m2][n2][rh * 2 + h], 0.f);
                    ull k = packkey(d, nw * 64 + n2 * 8 + (lane & 3) * 2 + h);
                    best = (k < best) ? k : best;
                }
            ull o = __shfl_xor_sync(0xffffffffu, best, 1); best = (o < best) ? o : best;
            o = __shfl_xor_sync(0xffffffffu, best, 2);     best = (o < best) ? o : best;
            if ((lane & 3) == 0)
                atomicMin(&rowKey[(mw * 2 + m2) * 16 + (lane >> 2) + rh * 8], best);
        }

#pragma unroll
    for (int n2 = 0; n2 < 8; n2++)
#pragma unroll
        for (int h = 0; h < 2; h++) {
            ull best = ~0ULL;
#pragma unroll
            for (int m2 = 0; m2 < 2; m2++)
#pragma unroll
                for (int rh = 0; rh < 2; rh++) {
                    float d = fmaxf(naR[m2][rh] + nbC[n2][h] - 2.f * acc[m2][n2][rh * 2 + h], 0.f);
                    ull k = packkey(d, mo + (mw * 2 + m2) * 16 + (lane >> 2) + rh * 8);
                    best = (k < best) ? k : best;
                }
            ull o = __shfl_xor_sync(0xffffffffu, best, 4);  best = (o < best) ? o : best;
            o = __shfl_xor_sync(0xffffffffu, best, 8);      best = (o < best) ? o : best;
            o = __shfl_xor_sync(0xffffffffu, best, 16);     best = (o < best) ? o : best;
            if (lane < 4)
                atomicMin(&colKey[nw * 64 + n2 * 8 + (lane & 3) * 2 + h], best);
        }
    __syncthreads();
    if (tid < 64) g_key_fg[(size_t)bb * LG + mo + tid] = rowKey[tid];
    atomicMin(&g_key_fl[(size_t)bb * LL + tid], colKey[tid]);
}

// ================= fused top-k selection + gathered MSE =================
// grid (NB, 4), 576 threads: rank-select with ballot compaction, then MSE.
__global__ void __launch_bounds__(576) selmse_kernel(const float* __restrict__ fG,
                                                     const float* __restrict__ fL) {
    int bb = blockIdx.x, which = blockIdx.y;
    const ull* keys; const float* fin; const float* fc;
    int Lin, Lc, Msel;
    if (which == 0)      { keys = g_key_fg; fin = fG; fc = fL; Lin = LG; Lc = LL; Msel = MG; }
    else if (which == 1) { keys = g_key_fl; fin = fL; fc = fG; Lin = LL; Lc = LG; Msel = ML; }
    else if (which == 2) { keys = g_key_gg; fin = fG; fc = fL; Lin = LG; Lc = LL; Msel = MG; }
    else                 { keys = g_key_gl; fin = fL; fc = fG; Lin = LL; Lc = LG; Msel = ML; }
    int accIdx = 5 + which;

    __shared__ ull sk[LG];
    __shared__ int selsh[MG];
    __shared__ int candsh[MG];
    __shared__ int warpcnt[18];
    __shared__ float shred[20];

    int tid = threadIdx.x, lane = tid & 31, wid = tid >> 5;
    if (tid < Lin) sk[tid] = keys[(size_t)bb * Lin + tid];
    __syncthreads();

    int myflag = 0;
    if (tid < Lin) {
        ull mine = sk[tid];
        int cnt = 0;
#pragma unroll 8
        for (int j = 0; j < Lin; j++) {
            ull o = sk[j];
            cnt += (o < mine) || (o == mine && j < tid);
        }
        myflag = (cnt < Msel) ? 1 : 0;
    }
    u32 bal = __ballot_sync(0xffffffffu, myflag);
    if (lane == 0) warpcnt[wid] = __popc(bal);
    __syncthreads();
    if (myflag) {
        int pos = __popc(bal & ((1u << lane) - 1u));
        for (int w = 0; w < wid; w++) pos += warpcnt[w];
        selsh[pos] = tid;
        candsh[pos] = (int)(sk[tid] & 0xffffffffULL);
    }
    __syncthreads();

    const float4* fin4 = (const float4*)(fin + (size_t)bb * Lin * NC);
    const float4* fc4  = (const float4*)(fc + (size_t)bb * Lc * NC);
    float s = 0.f;
    int total = Msel * (NC / 4);
    for (int idx = tid; idx < total; idx += 576) {
        int mi = idx >> 7, t = idx & 127;
        int row = selsh[mi], cand = candsh[mi];
        float4 x = fin4[row * 128 + t], y = fc4[cand * 128 + t];
        float dx = x.x - y.x, dy = x.y - y.y, dz = x.z - y.z, dw = x.w - y.w;
        s += dx * dx + dy * dy + dz * dz + dw * dw;
    }
#pragma unroll
    for (int o = 16; o; o >>= 1) s += __shfl_down_sync(0xffffffffu, s, o);
    if (lane == 0) shred[wid] = s;
    __syncthreads();
    if (wid == 0) {
        float r = (lane < 18) ? shred[lane] : 0.f;
#pragma unroll
        for (int o = 16; o; o >>= 1) r += __shfl_down_sync(0xffffffffu, r, o);
        if (lane == 0) atomicAdd(&g_acc[accIdx], r);
    }
}

// ================= final combine =================
__global__ void final_kernel(float* __restrict__ out, int out_size) {
    __shared__ float sR[1024];
    __shared__ float rowsum[32];
    __shared__ float sh[8];
    __shared__ float covG[2];
    __shared__ float qsh;
    for (int mat = 0; mat < 2; mat++) {
        for (int t = threadIdx.x; t < 1024; t += blockDim.x) {
            float s = 0.f;
            for (int c = 0; c < 32; c++) s += g_Rp[mat][c][t];
            sR[t] = s;
        }
        __syncthreads();
        if (threadIdx.x < 32) {
            float s = 0.f;
            for (int k = 0; k < 32; k++) s += sR[threadIdx.x * 32 + k];
            rowsum[threadIdx.x] = s;
        }
        __syncthreads();
        if (threadIdx.x == 0) {
            float t = 0.f;
            for (int i = 0; i < 32; i++) t += rowsum[i];
            qsh = t * (1.f / 1024.f);
        }
        __syncthreads();
        float q = qsh;
        float part = 0.f;
        for (int t = threadIdx.x; t < 1024; t += blockDim.x) {
            int i = t >> 5, k = t & 31;
            float g = sR[t] - rowsum[i] * (1.f / 32.f) - rowsum[k] * (1.f / 32.f) + q;
            part += g * g;
        }
        float tot = block_reduce(part, sh);
        if (threadIdx.x == 0) covG[mat] = tot;
        __syncthreads();
    }
    if (threadIdx.x == 0) {
        float inv_g = g_acc[4] * (1.f / (32.f * 8192.f));
        float v = 0.5f * (g_acc[0] + g_acc[1]) * (1.f / 8192.f);
        float cov = ((covG[0] - g_acc[2]) + (covG[1] - g_acc[3])) * (1.f / (31.f * 31.f * 8192.f));
        float global_loss = 25.f * inv_g + 25.f * v + 1.f * cov;
        float mfg = g_acc[5] * (1.f / (32.f * MG * NC));
        float mfl = g_acc[6] * (1.f / (32.f * ML * NC));
        float mgg = g_acc[7] * (1.f / (32.f * MG * NC));
        float mgl = g_acc[8] * (1.f / (32.f * ML * NC));
        float local_loss = 25.f * (0.5f * (mfg + mfl) + 0.5f * (mgg + mgl));
        float res = 0.25f * global_loss + 0.75f * local_loss;
        for (int i = 0; i < out_size; i++) out[i] = res;
    }
}

extern "C" void kernel_launch(void* const* d_in, const int* in_sizes, int n_in,
                              void* d_out, int out_size) {
    (void)in_sizes; (void)n_in;
    const float* zg = (const float*)d_in[0];   // (32, 8192)
    const float* zl = (const float*)d_in[1];   // (32, 8192)
    const float* fg = (const float*)d_in[2];   // (32, 576, 512)
    const float* fl = (const float*)d_in[3];   // (32, 256, 512)
    const float* gg = (const float*)d_in[4];   // (32, 576, 2)
    const float* gl = (const float*)d_in[5];   // (32, 256, 2)
    float* out = (float*)d_out;

    fused_pre<<<289, 256>>>(zg, zl, fg, fl, gg, gl);

    {
        dim3 grid(LG / 64, NB);
        cdist_mma<<<grid, 256>>>(fg, fl);
    }
    {
        dim3 grid(NB, 4);
        selmse_kernel<<<grid, 576>>>(fg, fl);
    }
    final_kernel<<<1, 256>>>(out, out_size);
}

// round 7
// speedup vs baseline: 3.6767x; 1.1970x over previous
#include <cuda_runtime.h>

typedef unsigned long long ull;
typedef unsigned int u32;

#define NB 32
#define LG 576
#define LL 256
#define NC 512
#define ND 8192
#define MG 20
#define ML 4

// ---------------- device scratch (no allocations allowed) ----------------
__device__ ull   g_key_fg[NB * LG];
__device__ ull   g_key_fl[NB * LL];
__device__ ull   g_key_gg[NB * LG];
__device__ ull   g_key_gl[NB * LL];
__device__ float g_normg[NB * LG];
__device__ float g_norml[NB * LL];
__device__ float g_Rp[2][32][1024];
__device__ float g_R[2][1024];
__device__ float g_acc[16];
// acc: 0 var_a, 1 var_b, 2 sum s_j^2 a, 3 sum s_j^2 b, 4 inv-sum,
//      5 mse_fg, 6 mse_fl, 7 mse_gg, 8 mse_gl

__device__ __forceinline__ ull packkey(float d, int i) {
    return (((ull)__float_as_uint(d)) << 32) | (unsigned)i;
}

#define MMA_TF32(C, A, B0, B1)                                              \
    asm volatile("mma.sync.aligned.m16n8k8.row.col.f32.tf32.tf32.f32 "      \
                 "{%0,%1,%2,%3}, {%4,%5,%6,%7}, {%8,%9}, {%0,%1,%2,%3};"    \
                 : "+f"((C)[0]), "+f"((C)[1]), "+f"((C)[2]), "+f"((C)[3])   \
                 : "r"((A)[0]), "r"((A)[1]), "r"((A)[2]), "r"((A)[3]),      \
                   "r"(B0), "r"(B1))

__device__ __forceinline__ void cpa16(u32 dst, const void* src) {
    asm volatile("cp.async.ca.shared.global [%0], [%1], 16;" :: "r"(dst), "l"(src));
}
#define CP_COMMIT() asm volatile("cp.async.commit_group;" ::: "memory")

__device__ float block_reduce(float v, float* sh) {
    __syncthreads();
    int lane = threadIdx.x & 31, wid = threadIdx.x >> 5;
#pragma unroll
    for (int o = 16; o; o >>= 1) v += __shfl_down_sync(0xffffffffu, v, o);
    if (lane == 0) sh[wid] = v;
    __syncthreads();
    float r = 0.f;
    if (wid == 0) {
        int nw = (blockDim.x + 31) >> 5;
        r = (lane < nw) ? sh[lane] : 0.f;
#pragma unroll
        for (int o = 16; o; o >>= 1) r += __shfl_down_sync(0xffffffffu, r, o);
    }
    return r;  // valid on thread 0
}

// ================= fused pre-kernel =================
// blocks 0..31: per-dim VICReg stats; 32..95: split-K gram; 96..127: fl norms;
// 128..223: fg norms; 224: init; 225..288: grid-space NN (32 batches x 2 dirs).
__global__ void __launch_bounds__(256) fused_pre(const float* __restrict__ za,
                                                 const float* __restrict__ zb,
                                                 const float* __restrict__ fg,
                                                 const float* __restrict__ fl,
                                                 const float* __restrict__ gg_in,
                                                 const float* __restrict__ gl_in) {
    __shared__ float sh[8];
    int blk = blockIdx.x, tid = threadIdx.x;
    if (blk < 32) {
        int j = blk * 256 + tid;
        float sa = 0, sqa = 0, sb = 0, sqb = 0, sd = 0;
#pragma unroll 8
        for (int i = 0; i < 32; i++) {
            float x = za[(size_t)i * ND + j], y = zb[(size_t)i * ND + j];
            sa += x; sqa += x * x; sb += y; sqb += y * y;
            float df = x - y; sd += df * df;
        }
        float s_a = sqa - sa * sa * (1.f / 32.f);
        float s_b = sqb - sb * sb * (1.f / 32.f);
        float va = fmaxf(0.f, 1.f - sqrtf(s_a * (1.f / 31.f) + 1e-4f));
        float vb = fmaxf(0.f, 1.f - sqrtf(s_b * (1.f / 31.f) + 1e-4f));
        float r;
        r = block_reduce(va, sh);        if (tid == 0) atomicAdd(&g_acc[0], r);
        r = block_reduce(vb, sh);        if (tid == 0) atomicAdd(&g_acc[1], r);
        r = block_reduce(s_a * s_a, sh); if (tid == 0) atomicAdd(&g_acc[2], r);
        r = block_reduce(s_b * s_b, sh); if (tid == 0) atomicAdd(&g_acc[3], r);
        r = block_reduce(sd, sh);        if (tid == 0) atomicAdd(&g_acc[4], r);
    } else if (blk < 96) {
        __shared__ float s[32][257];
        int idx = blk - 32;
        int mat = idx >> 5, chunk = idx & 31;
        int d0 = chunk * 256;
        const float* z = mat ? zb : za;
        for (int i = tid; i < 2048; i += 256) {
            int row = i >> 6, c4 = i & 63;
            float4 v = *(const float4*)(z + (size_t)row * ND + d0 + c4 * 4);
            s[row][c4 * 4 + 0] = v.x; s[row][c4 * 4 + 1] = v.y;
            s[row][c4 * 4 + 2] = v.z; s[row][c4 * 4 + 3] = v.w;
        }
        __syncthreads();
        int ia = tid >> 3, kb = (tid & 7) * 4;
        float c[4] = {};
        for (int d = 0; d < 256; d++) {
            float av = s[ia][d];
#pragma unroll
            for (int j = 0; j < 4; j++) c[j] = fmaf(av, s[kb + j][d], c[j]);
        }
#pragma unroll
        for (int j = 0; j < 4; j++) g_Rp[mat][chunk][ia * 32 + kb + j] = c[j];
    } else if (blk < 224) {
        const float* src; float* dst; int rows, w, wtot;
        if (blk < 128) { src = fl; dst = g_norml; rows = NB * LL; w = (blk - 96) * 8 + (tid >> 5); wtot = 32 * 8; }
        else           { src = fg; dst = g_normg; rows = NB * LG; w = (blk - 128) * 8 + (tid >> 5); wtot = 96 * 8; }
        int lane = tid & 31;
        for (int row = w; row < rows; row += wtot) {
            const float4* p = (const float4*)(src + (size_t)row * NC);
            float s = 0.f;
#pragma unroll
            for (int i = 0; i < 4; i++) {
                float4 v = p[lane + i * 32];
                s += v.x * v.x + v.y * v.y + v.z * v.z + v.w * v.w;
            }
#pragma unroll
            for (int o = 16; o; o >>= 1) s += __shfl_down_sync(0xffffffffu, s, o);
            if (lane == 0) dst[row] = s;
        }
    } else if (blk == 224) {
        if (tid < 16) g_acc[tid] = 0.f;
        for (int i = tid; i < NB * LL; i += 256) g_key_fl[i] = ~0ULL;
    } else {
        // grid-space NN (select happens later in selmse)
        int idx = blk - 225;
        int bb = idx >> 1, dir = idx & 1;
        int Lin = dir ? LL : LG, Lc = dir ? LG : LL;
        const float* gin   = dir ? gl_in : gg_in;
        const float* gcand = dir ? gg_in : gl_in;
        ull* keyout = dir ? g_key_gl : g_key_gg;
        __shared__ float2 sc[LG];
        const float2* gc = (const float2*)gcand + (size_t)bb * Lc;
        for (int i = tid; i < Lc; i += 256) sc[i] = gc[i];
        __syncthreads();
        const float2* gi = (const float2*)gin + (size_t)bb * Lin;
        for (int l = tid; l < Lin; l += 256) {
            float2 g = gi[l];
            float best = 3.4e38f; int bi = 0;
            for (int m = 0; m < Lc; m++) {
                float dx = g.x - sc[m].x, dy = g.y - sc[m].y;
                float d = dx * dx + dy * dy;
                if (d < best) { best = d; bi = m; }
            }
            keyout[(size_t)bb * Lin + l] = packkey(best, bi);
        }
    }
}

// ================= tensor-core cdist^2 + row/col argmin =================
// cp.async double-buffered, K-chunk 16, raw f32 bits as tf32 (HW truncates).
__global__ void __launch_bounds__(256, 3) cdist_mma(const float* __restrict__ Ag,
                                                    const float* __restrict__ Bg) {
    int bb = blockIdx.y;
    int mo = blockIdx.x * 64;
    const float* A = Ag + (size_t)bb * LG * NC;
    const float* B = Bg + (size_t)bb * LL * NC;

    __shared__ u32 As[2][2 * 4 * 4 * 32];    // [stage][ks][mfrag][reg][lane^swz]  (4 KB/stage)
    __shared__ u32 Bs[2][2 * 32 * 2 * 32];   // [stage][ks][nfrag][reg][lane^swz] (16 KB/stage)
    __shared__ ull rowKey[64];
    __shared__ ull colKey[LL];

    int tid = threadIdx.x, lane = tid & 31, warp = tid >> 5;
    int mw = warp >> 2, nw = warp & 3;
    if (tid < 64) rowKey[tid] = ~0ULL;
    colKey[tid] = ~0ULL;

    // per-thread cp.async roles
    int ar = tid >> 2, ac0 = (tid & 3) * 4;                    // A: 64 rows x 16 k
    int aks = ac0 >> 3, ahalf = (ac0 & 7) >> 2;
    int areg = ahalf * 2 + ((ar & 15) >> 3);
    int alb = ((ar & 7) * 4) ^ (aks << 2) ^ (ahalf << 4);
    int aoff = (((aks * 4 + (ar >> 4)) * 4 + areg) * 32) + alb;
    const float* aptr = A + (size_t)(mo + ar) * NC + ac0;

    u32 asb[2], bsb[2];
    asb[0] = (u32)__cvta_generic_to_shared(&As[0][0]);
    asb[1] = (u32)__cvta_generic_to_shared(&As[1][0]);
    bsb[0] = (u32)__cvta_generic_to_shared(&Bs[0][0]);
    bsb[1] = (u32)__cvta_generic_to_shared(&Bs[1][0]);

    int boff[4]; const float* bptr[4];
#pragma unroll
    for (int i = 0; i < 4; i++) {
        int f = tid + i * 256;
        int n = f >> 2, c0 = (f & 3) * 4;
        int ks = c0 >> 3, reg = (c0 & 7) >> 2;
        int lb = ((n & 7) * 4) ^ (ks << 2) ^ (reg << 4);
        boff[i] = (((ks * 32 + (n >> 3)) * 2 + reg) * 32) + lb;
        bptr[i] = B + (size_t)n * NC + c0;
    }

#define LOAD_STAGE(CH, ST)                                                   \
    do {                                                                     \
        int koff_ = (CH) * 16;                                               \
        cpa16(asb[ST] + aoff * 4, aptr + koff_);                             \
        _Pragma("unroll")                                                    \
        for (int i_ = 0; i_ < 4; i_++)                                       \
            cpa16(bsb[ST] + boff[i_] * 4, bptr[i_] + koff_);                 \
        CP_COMMIT();                                                         \
    } while (0)

    float acc[2][8][4];
#pragma unroll
    for (int i = 0; i < 2; i++)
#pragma unroll
        for (int j = 0; j < 8; j++)
#pragma unroll
            for (int k = 0; k < 4; k++) acc[i][j][k] = 0.f;

    LOAD_STAGE(0, 0);
    LOAD_STAGE(1, 1);

    for (int ch = 0; ch < 32; ch++) {
        if (ch < 31) asm volatile("cp.async.wait_group 1;" ::: "memory");
        else         asm volatile("cp.async.wait_group 0;" ::: "memory");
        __syncthreads();
        int st = ch & 1;
        const u32* as = As[st];
        const u32* bs = Bs[st];
#pragma unroll
        for (int ks = 0; ks < 2; ks++) {
            u32 a[2][4];
#pragma unroll
            for (int m2 = 0; m2 < 2; m2++) {
                int mf = mw * 2 + m2;
                int base = ((ks * 4 + mf) * 4) * 32;
#pragma unroll
                for (int rg = 0; rg < 4; rg++)
                    a[m2][rg] = as[base + rg * 32 + (lane ^ (ks << 2) ^ ((rg >> 1) << 4))];
            }
#pragma unroll
            for (int n2 = 0; n2 < 8; n2++) {
                int nf = nw * 8 + n2;
                u32 b0 = bs[((ks * 32 + nf) * 2 + 0) * 32 + (lane ^ (ks << 2))];
                u32 b1 = bs[((ks * 32 + nf) * 2 + 1) * 32 + (lane ^ (ks << 2) ^ 16)];
                MMA_TF32(acc[0][n2], a[0], b0, b1);
                MMA_TF32(acc[1][n2], a[1], b0, b1);
            }
        }
        __syncthreads();
        if (ch + 2 < 32) LOAD_STAGE(ch + 2, st);
    }

    // ---- epilogue: d2 = na + nb - 2*dot, packed-key argmins ----
    float naR[2][2], nbC[8][2];
#pragma unroll
    for (int m2 = 0; m2 < 2; m2++)
#pragma unroll
        for (int rh = 0; rh < 2; rh++)
            naR[m2][rh] = g_normg[bb * LG + mo + (mw * 2 + m2) * 16 + (lane >> 2) + rh * 8];
#pragma unroll
    for (int n2 = 0; n2 < 8; n2++)
#pragma unroll
        for (int h = 0; h < 2; h++)
            nbC[n2][h] = g_norml[bb * LL + nw * 64 + n2 * 8 + (lane & 3) * 2 + h];

#pragma unroll
    for (int m2 = 0; m2 < 2; m2++)
#pragma unroll
        for (int rh = 0; rh < 2; rh++) {
            ull best = ~0ULL;
#pragma unroll
            for (int n2 = 0; n2 < 8; n2++)
#pragma unroll
                for (int h = 0; h < 2; h++) {
                    float d = fmaxf(naR[m2][rh] + nbC[n2][h] - 2.f * acc[m2][n2][rh * 2 + h], 0.f);
                    ull k = packkey(d, nw * 64 + n2 * 8 + (lane & 3) * 2 + h);
                    best = (k < best) ? k : best;
                }
            ull o = __shfl_xor_sync(0xffffffffu, best, 1); best = (o < best) ? o : best;
            o = __shfl_xor_sync(0xffffffffu, best, 2);     best = (o < best) ? o : best;
            if ((lane & 3) == 0)
                atomicMin(&rowKey[(mw * 2 + m2) * 16 + (lane >> 2) + rh * 8], best);
        }

#pragma unroll
    for (int n2 = 0; n2 < 8; n2++)
#pragma unroll
        for (int h = 0; h < 2; h++) {
            ull best = ~0ULL;
#pragma unroll
            for (int m2 = 0; m2 < 2; m2++)
#pragma unroll
                for (int rh = 0; rh < 2; rh++) {
                    float d = fmaxf(naR[m2][rh] + nbC[n2][h] - 2.f * acc[m2][n2][rh * 2 + h], 0.f);
                    ull k = packkey(d, mo + (mw * 2 + m2) * 16 + (lane >> 2) + rh * 8);
                    best = (k < best) ? k : best;
                }
            ull o = __shfl_xor_sync(0xffffffffu, best, 4);  best = (o < best) ? o : best;
            o = __shfl_xor_sync(0xffffffffu, best, 8);      best = (o < best) ? o : best;
            o = __shfl_xor_sync(0xffffffffu, best, 16);     best = (o < best) ? o : best;
            if (lane < 4)
                atomicMin(&colKey[nw * 64 + n2 * 8 + (lane & 3) * 2 + h], best);
        }
    __syncthreads();
    if (tid < 64) g_key_fg[(size_t)bb * LG + mo + tid] = rowKey[tid];
    atomicMin(&g_key_fl[(size_t)bb * LL + tid], colKey[tid]);
}

// ================= fused top-k selection + gathered MSE + gram reduction =================
// grid (NB, 5): which<4 => rank-select + MSE; which==4 => parallel g_Rp reduction.
__global__ void __launch_bounds__(576) selmse_kernel(const float* __restrict__ fG,
                                                     const float* __restrict__ fL) {
    int bb = blockIdx.x, which = blockIdx.y;
    if (which == 4) {
        // 32 blocks x 64 entries: reduce g_Rp[mat][0..31][e] -> g_R[mat][e]
        int t = threadIdx.x;
        if (t < 64) {
            int e = bb * 64 + t;       // flattened 0..2047
            int mat = e >> 10, idx = e & 1023;
            float s = 0.f;
#pragma unroll
            for (int c = 0; c < 32; c++) s += g_Rp[mat][c][idx];
            g_R[mat][idx] = s;
        }
        return;
    }

    const ull* keys; const float* fin; const float* fc;
    int Lin, Lc, Msel;
    if (which == 0)      { keys = g_key_fg; fin = fG; fc = fL; Lin = LG; Lc = LL; Msel = MG; }
    else if (which == 1) { keys = g_key_fl; fin = fL; fc = fG; Lin = LL; Lc = LG; Msel = ML; }
    else if (which == 2) { keys = g_key_gg; fin = fG; fc = fL; Lin = LG; Lc = LL; Msel = MG; }
    else                 { keys = g_key_gl; fin = fL; fc = fG; Lin = LL; Lc = LG; Msel = ML; }
    int accIdx = 5 + which;

    __shared__ ull sk[LG];
    __shared__ int selsh[MG];
    __shared__ int candsh[MG];
    __shared__ int warpcnt[18];
    __shared__ float shred[20];

    int tid = threadIdx.x, lane = tid & 31, wid = tid >> 5;
    if (tid < Lin) sk[tid] = keys[(size_t)bb * Lin + tid];
    __syncthreads();

    int myflag = 0;
    if (tid < Lin) {
        ull mine = sk[tid];
        int cnt = 0;
#pragma unroll 8
        for (int j = 0; j < Lin; j++) {
            ull o = sk[j];
            cnt += (o < mine) || (o == mine && j < tid);
        }
        myflag = (cnt < Msel) ? 1 : 0;
    }
    u32 bal = __ballot_sync(0xffffffffu, myflag);
    if (lane == 0) warpcnt[wid] = __popc(bal);
    __syncthreads();
    if (myflag) {
        int pos = __popc(bal & ((1u << lane) - 1u));
        for (int w = 0; w < wid; w++) pos += warpcnt[w];
        selsh[pos] = tid;
        candsh[pos] = (int)(sk[tid] & 0xffffffffULL);
    }
    __syncthreads();

    const float4* fin4 = (const float4*)(fin + (size_t)bb * Lin * NC);
    const float4* fc4  = (const float4*)(fc + (size_t)bb * Lc * NC);
    float s = 0.f;
    int total = Msel * (NC / 4);
    for (int idx = tid; idx < total; idx += 576) {
        int mi = idx >> 7, t = idx & 127;
        int row = selsh[mi], cand = candsh[mi];
        float4 x = fin4[row * 128 + t], y = fc4[cand * 128 + t];
        float dx = x.x - y.x, dy = x.y - y.y, dz = x.z - y.z, dw = x.w - y.w;
        s += dx * dx + dy * dy + dz * dz + dw * dw;
    }
#pragma unroll
    for (int o = 16; o; o >>= 1) s += __shfl_down_sync(0xffffffffu, s, o);
    if (lane == 0) shred[wid] = s;
    __syncthreads();
    if (wid == 0) {
        float r = (lane < 18) ? shred[lane] : 0.f;
#pragma unroll
        for (int o = 16; o; o >>= 1) r += __shfl_down_sync(0xffffffffu, r, o);
        if (lane == 0) atomicAdd(&g_acc[accIdx], r);
    }
}

// ================= final combine =================
__global__ void final_kernel(float* __restrict__ out, int out_size) {
    __shared__ float sR[1024];
    __shared__ float rowsum[32];
    __shared__ float sh[8];
    __shared__ float covG[2];
    __shared__ float qsh;
    for (int mat = 0; mat < 2; mat++) {
        for (int t = threadIdx.x; t < 1024; t += blockDim.x) sR[t] = g_R[mat][t];
        __syncthreads();
        if (threadIdx.x < 32) {
            float s = 0.f;
            for (int k = 0; k < 32; k++) s += sR[threadIdx.x * 32 + k];
            rowsum[threadIdx.x] = s;
        }
        __syncthreads();
        if (threadIdx.x == 0) {
            float t = 0.f;
            for (int i = 0; i < 32; i++) t += rowsum[i];
            qsh = t * (1.f / 1024.f);
        }
        __syncthreads();
        float q = qsh;
        float part = 0.f;
        for (int t = threadIdx.x; t < 1024; t += blockDim.x) {
            int i = t >> 5, k = t & 31;
            float g = sR[t] - rowsum[i] * (1.f / 32.f) - rowsum[k] * (1.f / 32.f) + q;
            part += g * g;
        }
        float tot = block_reduce(part, sh);
        if (threadIdx.x == 0) covG[mat] = tot;
        __syncthreads();
    }
    if (threadIdx.x == 0) {
        float inv_g = g_acc[4] * (1.f / (32.f * 8192.f));
        float v = 0.5f * (g_acc[0] + g_acc[1]) * (1.f / 8192.f);
        float cov = ((covG[0] - g_acc[2]) + (covG[1] - g_acc[3])) * (1.f / (31.f * 31.f * 8192.f));
        float global_loss = 25.f * inv_g + 25.f * v + 1.f * cov;
        float mfg = g_acc[5] * (1.f / (32.f * MG * NC));
        float mfl = g_acc[6] * (1.f / (32.f * ML * NC));
        float mgg = g_acc[7] * (1.f / (32.f * MG * NC));
        float mgl = g_acc[8] * (1.f / (32.f * ML * NC));
        float local_loss = 25.f * (0.5f * (mfg + mfl) + 0.5f * (mgg + mgl));
        float res = 0.25f * global_loss + 0.75f * local_loss;
        for (int i = 0; i < out_size; i++) out[i] = res;
    }
}

extern "C" void kernel_launch(void* const* d_in, const int* in_sizes, int n_in,
                              void* d_out, int out_size) {
    (void)in_sizes; (void)n_in;
    const float* zg = (const float*)d_in[0];   // (32, 8192)
    const float* zl = (const float*)d_in[1];   // (32, 8192)
    const float* fg = (const float*)d_in[2];   // (32, 576, 512)
    const float* fl = (const float*)d_in[3];   // (32, 256, 512)
    const float* gg = (const float*)d_in[4];   // (32, 576, 2)
    const float* gl = (const float*)d_in[5];   // (32, 256, 2)
    float* out = (float*)d_out;

    fused_pre<<<289, 256>>>(zg, zl, fg, fl, gg, gl);

    {
        dim3 grid(LG / 64, NB);
        cdist_mma<<<grid, 256>>>(fg, fl);
    }
    {
        dim3 grid(NB, 5);
        selmse_kernel<<<grid, 576>>>(fg, fl);
    }
    final_kernel<<<1, 256>>>(out, out_size);
}

// round 8
// speedup vs baseline: 4.7174x; 1.2831x over previous
#include <cuda_runtime.h>

typedef unsigned long long ull;
typedef unsigned int u32;

#define NB 32
#define LG 576
#define LL 256
#define NC 512
#define ND 8192
#define MG 20
#define ML 4

// ---------------- device scratch (no allocations allowed) ----------------
__device__ ull   g_key_fg[NB * LG];
__device__ ull   g_key_fl[NB * LL];
__device__ ull   g_key_gg[NB * LG];
__device__ ull   g_key_gl[NB * LL];
__device__ float g_normg[NB * LG];
__device__ float g_norml[NB * LL];
__device__ u32   g_fgb[NB * LG * NC / 2];   // bf16x2 copy of fg (18.9 MB)
__device__ u32   g_flb[NB * LL * NC / 2];   // bf16x2 copy of fl (8.4 MB)
__device__ float g_Rp[2][32][1024];
__device__ float g_R[2][1024];
__device__ float g_acc[16];
// acc: 0 var_a, 1 var_b, 2 sum s_j^2 a, 3 sum s_j^2 b, 4 inv-sum,
//      5 mse_fg, 6 mse_fl, 7 mse_gg, 8 mse_gl

__device__ __forceinline__ ull packkey(float d, int i) {
    return (((ull)__float_as_uint(d)) << 32) | (unsigned)i;
}

#define MMA_BF16(C, A, B0, B1)                                              \
    asm volatile("mma.sync.aligned.m16n8k16.row.col.f32.bf16.bf16.f32 "     \
                 "{%0,%1,%2,%3}, {%4,%5,%6,%7}, {%8,%9}, {%0,%1,%2,%3};"    \
                 : "+f"((C)[0]), "+f"((C)[1]), "+f"((C)[2]), "+f"((C)[3])   \
                 : "r"((A)[0]), "r"((A)[1]), "r"((A)[2]), "r"((A)[3]),      \
                   "r"(B0), "r"(B1))

__device__ __forceinline__ void cpa16(u32 dst, const void* src) {
    asm volatile("cp.async.ca.shared.global [%0], [%1], 16;" :: "r"(dst), "l"(src));
}
#define CP_COMMIT() asm volatile("cp.async.commit_group;" ::: "memory")

__device__ __forceinline__ u32 packbf(float lo, float hi) {
    u32 r; asm("cvt.rn.bf16x2.f32 %0, %1, %2;" : "=r"(r) : "f"(hi), "f"(lo)); return r;
}

__device__ float block_reduce(float v, float* sh) {
    __syncthreads();
    int lane = threadIdx.x & 31, wid = threadIdx.x >> 5;
#pragma unroll
    for (int o = 16; o; o >>= 1) v += __shfl_down_sync(0xffffffffu, v, o);
    if (lane == 0) sh[wid] = v;
    __syncthreads();
    float r = 0.f;
    if (wid == 0) {
        int nw = (blockDim.x + 31) >> 5;
        r = (lane < nw) ? sh[lane] : 0.f;
#pragma unroll
        for (int o = 16; o; o >>= 1) r += __shfl_down_sync(0xffffffffu, r, o);
    }
    return r;  // valid on thread 0
}

// ================= fused pre-kernel =================
// blocks 0..31: per-dim VICReg stats; 32..95: split-K gram; 96..127: fl norms+bf16;
// 128..223: fg norms+bf16; 224: init; 225..288: grid-space NN.
__global__ void __launch_bounds__(256) fused_pre(const float* __restrict__ za,
                                                 const float* __restrict__ zb,
                                                 const float* __restrict__ fg,
                                                 const float* __restrict__ fl,
                                                 const float* __restrict__ gg_in,
                                                 const float* __restrict__ gl_in) {
    __shared__ float sh[8];
    int blk = blockIdx.x, tid = threadIdx.x;
    if (blk < 32) {
        int j = blk * 256 + tid;
        float sa = 0, sqa = 0, sb = 0, sqb = 0, sd = 0;
#pragma unroll 8
        for (int i = 0; i < 32; i++) {
            float x = za[(size_t)i * ND + j], y = zb[(size_t)i * ND + j];
            sa += x; sqa += x * x; sb += y; sqb += y * y;
            float df = x - y; sd += df * df;
        }
        float s_a = sqa - sa * sa * (1.f / 32.f);
        float s_b = sqb - sb * sb * (1.f / 32.f);
        float va = fmaxf(0.f, 1.f - sqrtf(s_a * (1.f / 31.f) + 1e-4f));
        float vb = fmaxf(0.f, 1.f - sqrtf(s_b * (1.f / 31.f) + 1e-4f));
        float r;
        r = block_reduce(va, sh);        if (tid == 0) atomicAdd(&g_acc[0], r);
        r = block_reduce(vb, sh);        if (tid == 0) atomicAdd(&g_acc[1], r);
        r = block_reduce(s_a * s_a, sh); if (tid == 0) atomicAdd(&g_acc[2], r);
        r = block_reduce(s_b * s_b, sh); if (tid == 0) atomicAdd(&g_acc[3], r);
        r = block_reduce(sd, sh);        if (tid == 0) atomicAdd(&g_acc[4], r);
    } else if (blk < 96) {
        __shared__ float s[32][257];
        int idx = blk - 32;
        int mat = idx >> 5, chunk = idx & 31;
        int d0 = chunk * 256;
        const float* z = mat ? zb : za;
        for (int i = tid; i < 2048; i += 256) {
            int row = i >> 6, c4 = i & 63;
            float4 v = *(const float4*)(z + (size_t)row * ND + d0 + c4 * 4);
            s[row][c4 * 4 + 0] = v.x; s[row][c4 * 4 + 1] = v.y;
            s[row][c4 * 4 + 2] = v.z; s[row][c4 * 4 + 3] = v.w;
        }
        __syncthreads();
        int ia = tid >> 3, kb = (tid & 7) * 4;
        float c[4] = {};
        for (int d = 0; d < 256; d++) {
            float av = s[ia][d];
#pragma unroll
            for (int j = 0; j < 4; j++) c[j] = fmaf(av, s[kb + j][d], c[j]);
        }
#pragma unroll
        for (int j = 0; j < 4; j++) g_Rp[mat][chunk][ia * 32 + kb + j] = c[j];
    } else if (blk < 224) {
        const float* src; float* dst; u32* dbf; int rows, w, wtot;
        if (blk < 128) { src = fl; dst = g_norml; dbf = g_flb; rows = NB * LL; w = (blk - 96) * 8 + (tid >> 5); wtot = 32 * 8; }
        else           { src = fg; dst = g_normg; dbf = g_fgb; rows = NB * LG; w = (blk - 128) * 8 + (tid >> 5); wtot = 96 * 8; }
        int lane = tid & 31;
        for (int row = w; row < rows; row += wtot) {
            const float4* p = (const float4*)(src + (size_t)row * NC);
            u32* q = dbf + (size_t)row * (NC / 2);
            float s = 0.f;
#pragma unroll
            for (int i = 0; i < 4; i++) {
                float4 v = p[lane + i * 32];
                s += v.x * v.x + v.y * v.y + v.z * v.z + v.w * v.w;
                u32 lo = packbf(v.x, v.y), hi = packbf(v.z, v.w);
                *(uint2*)&q[(lane + i * 32) * 2] = make_uint2(lo, hi);
            }
#pragma unroll
            for (int o = 16; o; o >>= 1) s += __shfl_down_sync(0xffffffffu, s, o);
            if (lane == 0) dst[row] = s;
        }
    } else if (blk == 224) {
        if (tid < 16) g_acc[tid] = 0.f;
        for (int i = tid; i < NB * LL; i += 256) g_key_fl[i] = ~0ULL;
    } else {
        // grid-space NN (select happens later in selmse)
        int idx = blk - 225;
        int bb = idx >> 1, dir = idx & 1;
        int Lin = dir ? LL : LG, Lc = dir ? LG : LL;
        const float* gin   = dir ? gl_in : gg_in;
        const float* gcand = dir ? gg_in : gl_in;
        ull* keyout = dir ? g_key_gl : g_key_gg;
        __shared__ float2 sc[LG];
        const float2* gc = (const float2*)gcand + (size_t)bb * Lc;
        for (int i = tid; i < Lc; i += 256) sc[i] = gc[i];
        __syncthreads();
        const float2* gi = (const float2*)gin + (size_t)bb * Lin;
        for (int l = tid; l < Lin; l += 256) {
            float2 g = gi[l];
            float best = 3.4e38f; int bi = 0;
            for (int m = 0; m < Lc; m++) {
                float dx = g.x - sc[m].x, dy = g.y - sc[m].y;
                float d = dx * dx + dy * dy;
                if (d < best) { best = d; bi = m; }
            }
            keyout[(size_t)bb * Lin + l] = packkey(best, bi);
        }
    }
}

// ================= bf16 tensor-core cdist^2 + row/col argmin =================
// cp.async double-buffered, K-chunk 32 (bf16), m16n8k16. Same fragment-major
// swizzled smem layout as the tf32 version (indices identical in kpair units).
__global__ void __launch_bounds__(256, 2) cdist_mma(const u32* __restrict__ Ag,
                                                    const u32* __restrict__ Bg) {
    int bb = blockIdx.y;
    int mo = blockIdx.x * 64;
    const u32* A = Ag + (size_t)bb * LG * (NC / 2);
    const u32* B = Bg + (size_t)bb * LL * (NC / 2);

    __shared__ u32 As[2][2 * 4 * 4 * 32];    // [stage][ks][mfrag][reg][lane^swz]
    __shared__ u32 Bs[2][2 * 32 * 2 * 32];
    __shared__ ull rowKey[64];
    __shared__ ull colKey[LL];

    int tid = threadIdx.x, lane = tid & 31, warp = tid >> 5;
    int mw = warp >> 2, nw = warp & 3;
    if (tid < 64) rowKey[tid] = ~0ULL;
    colKey[tid] = ~0ULL;

    // per-thread cp.async roles (kpair units p0 behave like old f32 cols)
    int ar = tid >> 2, p0a = (tid & 3) * 4;                    // A: 64 rows x 32 bf16
    int aks = p0a >> 3, ahalf = (p0a & 7) >> 2;
    int areg = ahalf * 2 + ((ar & 15) >> 3);
    int alb = ((ar & 7) * 4) ^ (aks << 2) ^ (ahalf << 4);
    int aoff = (((aks * 4 + (ar >> 4)) * 4 + areg) * 32) + alb;
    const u32* aptr = A + (size_t)(mo + ar) * (NC / 2) + p0a;

    u32 asb[2], bsb[2];
    asb[0] = (u32)__cvta_generic_to_shared(&As[0][0]);
    asb[1] = (u32)__cvta_generic_to_shared(&As[1][0]);
    bsb[0] = (u32)__cvta_generic_to_shared(&Bs[0][0]);
    bsb[1] = (u32)__cvta_generic_to_shared(&Bs[1][0]);

    int boff[4]; const u32* bptr[4];
#pragma unroll
    for (int i = 0; i < 4; i++) {
        int f = tid + i * 256;
        int n = f >> 2, p0 = (f & 3) * 4;
        int ks = p0 >> 3, reg = (p0 & 7) >> 2;
        int lb = ((n & 7) * 4) ^ (ks << 2) ^ (reg << 4);
        boff[i] = (((ks * 32 + (n >> 3)) * 2 + reg) * 32) + lb;
        bptr[i] = B + (size_t)n * (NC / 2) + p0;
    }

#define LOAD_STAGE(CH, ST)                                                   \
    do {                                                                     \
        int koff_ = (CH) * 16;                                               \
        cpa16(asb[ST] + aoff * 4, aptr + koff_);                             \
        _Pragma("unroll")                                                    \
        for (int i_ = 0; i_ < 4; i_++)                                       \
            cpa16(bsb[ST] + boff[i_] * 4, bptr[i_] + koff_);                 \
        CP_COMMIT();                                                         \
    } while (0)

    float acc[2][8][4];
#pragma unroll
    for (int i = 0; i < 2; i++)
#pragma unroll
        for (int j = 0; j < 8; j++)
#pragma unroll
            for (int k = 0; k < 4; k++) acc[i][j][k] = 0.f;

    LOAD_STAGE(0, 0);
    LOAD_STAGE(1, 1);

    for (int ch = 0; ch < 16; ch++) {
        if (ch < 15) asm volatile("cp.async.wait_group 1;" ::: "memory");
        else         asm volatile("cp.async.wait_group 0;" ::: "memory");
        __syncthreads();
        int st = ch & 1;
        const u32* as = As[st];
        const u32* bs = Bs[st];
#pragma unroll
        for (int ks = 0; ks < 2; ks++) {
            u32 a[2][4];
#pragma unroll
            for (int m2 = 0; m2 < 2; m2++) {
                int mf = mw * 2 + m2;
                int base = ((ks * 4 + mf) * 4) * 32;
#pragma unroll
                for (int rg = 0; rg < 4; rg++)
                    a[m2][rg] = as[base + rg * 32 + (lane ^ (ks << 2) ^ ((rg >> 1) << 4))];
            }
#pragma unroll
            for (int n2 = 0; n2 < 8; n2++) {
                int nf = nw * 8 + n2;
                u32 b0 = bs[((ks * 32 + nf) * 2 + 0) * 32 + (lane ^ (ks << 2))];
                u32 b1 = bs[((ks * 32 + nf) * 2 + 1) * 32 + (lane ^ (ks << 2) ^ 16)];
                MMA_BF16(acc[0][n2], a[0], b0, b1);
                MMA_BF16(acc[1][n2], a[1], b0, b1);
            }
        }
        __syncthreads();
        if (ch + 2 < 16) LOAD_STAGE(ch + 2, st);
    }

    // ---- epilogue: d2 = na + nb - 2*dot, packed-key argmins ----
    float naR[2][2], nbC[8][2];
#pragma unroll
    for (int m2 = 0; m2 < 2; m2++)
#pragma unroll
        for (int rh = 0; rh < 2; rh++)
            naR[m2][rh] = g_normg[bb * LG + mo + (mw * 2 + m2) * 16 + (lane >> 2) + rh * 8];
#pragma unroll
    for (int n2 = 0; n2 < 8; n2++)
#pragma unroll
        for (int h = 0; h < 2; h++)
            nbC[n2][h] = g_norml[bb * LL + nw * 64 + n2 * 8 + (lane & 3) * 2 + h];

#pragma unroll
    for (int m2 = 0; m2 < 2; m2++)
#pragma unroll
        for (int rh = 0; rh < 2; rh++) {
            ull best = ~0ULL;
#pragma unroll
            for (int n2 = 0; n2 < 8; n2++)
#pragma unroll
                for (int h = 0; h < 2; h++) {
                    float d = fmaxf(naR[m2][rh] + nbC[n2][h] - 2.f * acc[m2][n2][rh * 2 + h], 0.f);
                    ull k = packkey(d, nw * 64 + n2 * 8 + (lane & 3) * 2 + h);
                    best = (k < best) ? k : best;
                }
            ull o = __shfl_xor_sync(0xffffffffu, best, 1); best = (o < best) ? o : best;
            o = __shfl_xor_sync(0xffffffffu, best, 2);     best = (o < best) ? o : best;
            if ((lane & 3) == 0)
                atomicMin(&rowKey[(mw * 2 + m2) * 16 + (lane >> 2) + rh * 8], best);
        }

#pragma unroll
    for (int n2 = 0; n2 < 8; n2++)
#pragma unroll
        for (int h = 0; h < 2; h++) {
            ull best = ~0ULL;
#pragma unroll
            for (int m2 = 0; m2 < 2; m2++)
#pragma unroll
                for (int rh = 0; rh < 2; rh++) {
                    float d = fmaxf(naR[m2][rh] + nbC[n2][h] - 2.f * acc[m2][n2][rh * 2 + h], 0.f);
                    ull k = packkey(d, mo + (mw * 2 + m2) * 16 + (lane >> 2) + rh * 8);
                    best = (k < best) ? k : best;
                }
            ull o = __shfl_xor_sync(0xffffffffu, best, 4);  best = (o < best) ? o : best;
            o = __shfl_xor_sync(0xffffffffu, best, 8);      best = (o < best) ? o : best;
            o = __shfl_xor_sync(0xffffffffu, best, 16);     best = (o < best) ? o : best;
            if (lane < 4)
                atomicMin(&colKey[nw * 64 + n2 * 8 + (lane & 3) * 2 + h], best);
        }
    __syncthreads();
    if (tid < 64) g_key_fg[(size_t)bb * LG + mo + tid] = rowKey[tid];
    atomicMin(&g_key_fl[(size_t)bb * LL + tid], colKey[tid]);
}

// ================= fused top-k selection + gathered MSE + gram reduction =================
__global__ void __launch_bounds__(576) selmse_kernel(const float* __restrict__ fG,
                                                     const float* __restrict__ fL) {
    int bb = blockIdx.x, which = blockIdx.y;
    if (which == 4) {
        int t = threadIdx.x;
        if (t < 64) {
            int e = bb * 64 + t;
            int mat = e >> 10, idx = e & 1023;
            float s = 0.f;
#pragma unroll
            for (int c = 0; c < 32; c++) s += g_Rp[mat][c][idx];
            g_R[mat][idx] = s;
        }
        return;
    }

    const ull* keys; const float* fin; const float* fc;
    int Lin, Lc, Msel;
    if (which == 0)      { keys = g_key_fg; fin = fG; fc = fL; Lin = LG; Lc = LL; Msel = MG; }
    else if (which == 1) { keys = g_key_fl; fin = fL; fc = fG; Lin = LL; Lc = LG; Msel = ML; }
    else if (which == 2) { keys = g_key_gg; fin = fG; fc = fL; Lin = LG; Lc = LL; Msel = MG; }
    else                 { keys = g_key_gl; fin = fL; fc = fG; Lin = LL; Lc = LG; Msel = ML; }
    int accIdx = 5 + which;

    __shared__ ull sk[LG];
    __shared__ int selsh[MG];
    __shared__ int candsh[MG];
    __shared__ int warpcnt[18];
    __shared__ float shred[20];

    int tid = threadIdx.x, lane = tid & 31, wid = tid >> 5;
    if (tid < Lin) sk[tid] = keys[(size_t)bb * Lin + tid];
    __syncthreads();

    int myflag = 0;
    if (tid < Lin) {
        ull mine = sk[tid];
        int cnt = 0;
#pragma unroll 8
        for (int j = 0; j < Lin; j++) {
            ull o = sk[j];
            cnt += (o < mine) || (o == mine && j < tid);
        }
        myflag = (cnt < Msel) ? 1 : 0;
    }
    u32 bal = __ballot_sync(0xffffffffu, myflag);
    if (lane == 0) warpcnt[wid] = __popc(bal);
    __syncthreads();
    if (myflag) {
        int pos = __popc(bal & ((1u << lane) - 1u));
        for (int w = 0; w < wid; w++) pos += warpcnt[w];
        selsh[pos] = tid;
        candsh[pos] = (int)(sk[tid] & 0xffffffffULL);
    }
    __syncthreads();

    const float4* fin4 = (const float4*)(fin + (size_t)bb * Lin * NC);
    const float4* fc4  = (const float4*)(fc + (size_t)bb * Lc * NC);
    float s = 0.f;
    int total = Msel * (NC / 4);
    for (int idx = tid; idx < total; idx += 576) {
        int mi = idx >> 7, t = idx & 127;
        int row = selsh[mi], cand = candsh[mi];
        float4 x = fin4[row * 128 + t], y = fc4[cand * 128 + t];
        float dx = x.x - y.x, dy = x.y - y.y, dz = x.z - y.z, dw = x.w - y.w;
        s += dx * dx + dy * dy + dz * dz + dw * dw;
    }
#pragma unroll
    for (int o = 16; o; o >>= 1) s += __shfl_down_sync(0xffffffffu, s, o);
    if (lane == 0) shred[wid] = s;
    __syncthreads();
    if (wid == 0) {
        float r = (lane < 18) ? shred[lane] : 0.f;
#pragma unroll
        for (int o = 16; o; o >>= 1) r += __shfl_down_sync(0xffffffffu, r, o);
        if (lane == 0) atomicAdd(&g_acc[accIdx], r);
    }
}

// ================= final combine (parallelized) =================
__global__ void __launch_bounds__(256) final_kernel(float* __restrict__ out, int out_size) {
    __shared__ float sR[1024];
    __shared__ float rowsum[32];
    __shared__ float sh[8];
    __shared__ float covG[2];
    __shared__ float qsh;
    int tid = threadIdx.x, lane = tid & 31, wid = tid >> 5;
    for (int mat = 0; mat < 2; mat++) {
        float4 v = ((const float4*)g_R[mat])[tid];
        *(float4*)&sR[tid * 4] = v;
        __syncthreads();
        // rowsums: 8 warps x 4 rows, warp-shuffle reduce
        for (int r = wid; r < 32; r += 8) {
            float s = sR[r * 32 + lane];
#pragma unroll
            for (int o = 16; o; o >>= 1) s += __shfl_down_sync(0xffffffffu, s, o);
            if (lane == 0) rowsum[r] = s;
        }
        __syncthreads();
        if (wid == 0) {
            float s = rowsum[lane];
#pragma unroll
            for (int o = 16; o; o >>= 1) s += __shfl_down_sync(0xffffffffu, s, o);
            if (lane == 0) qsh = s * (1.f / 1024.f);
        }
        __syncthreads();
        float q = qsh;
        float part = 0.f;
        int i = tid >> 3;                 // row of this thread's 4 entries
        float rsi = rowsum[i] * (1.f / 32.f);
#pragma unroll
        for (int j = 0; j < 4; j++) {
            int t = tid * 4 + j;
            int k = t & 31;
            float g = sR[t] - rsi - rowsum[k] * (1.f / 32.f) + q;
            part += g * g;
        }
        float tot = block_reduce(part, sh);
        if (tid == 0) covG[mat] = tot;
        __syncthreads();
    }
    if (tid == 0) {
        float inv_g = g_acc[4] * (1.f / (32.f * 8192.f));
        float v = 0.5f * (g_acc[0] + g_acc[1]) * (1.f / 8192.f);
        float cov = ((covG[0] - g_acc[2]) + (covG[1] - g_acc[3])) * (1.f / (31.f * 31.f * 8192.f));
        float global_loss = 25.f * inv_g + 25.f * v + 1.f * cov;
        float mfg = g_acc[5] * (1.f / (32.f * MG * NC));
        float mfl = g_acc[6] * (1.f / (32.f * ML * NC));
        float mgg = g_acc[7] * (1.f / (32.f * MG * NC));
        float mgl = g_acc[8] * (1.f / (32.f * ML * NC));
        float local_loss = 25.f * (0.5f * (mfg + mfl) + 0.5f * (mgg + mgl));
        float res = 0.25f * global_loss + 0.75f * local_loss;
        for (int i2 = 0; i2 < out_size; i2++) out[i2] = res;
    }
}

extern "C" void kernel_launch(void* const* d_in, const int* in_sizes, int n_in,
                              void* d_out, int out_size) {
    (void)in_sizes; (void)n_in;
    const float* zg = (const float*)d_in[0];   // (32, 8192)
    const float* zl = (const float*)d_in[1];   // (32, 8192)
    const float* fg = (const float*)d_in[2];   // (32, 576, 512)
    const float* fl = (const float*)d_in[3];   // (32, 256, 512)
    const float* gg = (const float*)d_in[4];   // (32, 576, 2)
    const float* gl = (const float*)d_in[5];   // (32, 256, 2)
    float* out = (float*)d_out;

    fused_pre<<<289, 256>>>(zg, zl, fg, fl, gg, gl);

    {
        dim3 grid(LG / 64, NB);
        u32* fgb; u32* flb;
        cudaGetSymbolAddress((void**)&fgb, g_fgb);
        cudaGetSymbolAddress((void**)&flb, g_flb);
        cdist_mma<<<grid, 256>>>(fgb, flb);
    }
    {
        dim3 grid(NB, 5);
        selmse_kernel<<<grid, 576>>>(fg, fl);
    }
    final_kernel<<<1, 256>>>(out, out_size);
}